// round 3
// baseline (speedup 1.0000x reference)
#include <cuda_runtime.h>
#include <cuda_bf16.h>
#include <math.h>

#define N_TABLES 26
#define ROWS_T   100001
#define EDIM     64
#define BATCH    8192
#define POOL_L   4
#define NFEAT    (N_TABLES + 1)          // 27
#define NPAIRS   (NFEAT * (NFEAT - 1) / 2) // 351
#define RDIM     (EDIM + NPAIRS)         // 415
#define FEAT_LD  (NFEAT * EDIM)          // 1728

// ---------------- scratch (device globals; no allocation allowed) ----------
__device__ float g_x1[BATCH * 512];
__device__ float g_x2[BATCH * 256];
__device__ float g_feat[BATCH * FEAT_LD];   // [b][27][64], feat 0 = bottom-MLP out
__device__ float g_R[BATCH * RDIM];
__device__ float g_z1[BATCH * 512];
__device__ float g_z2[BATCH * 256];

// ---------------- generic tiled SGEMM: C = relu?(A[M,K] * W[N,K]^T + bias) --
#define BM 64
#define BN 64
#define BKK 16

__global__ __launch_bounds__(256)
void gemm_bias_act(const float* __restrict__ A, int lda,
                   const float* __restrict__ W,      // [N,K] row-major
                   const float* __restrict__ bias,
                   float* __restrict__ C, int ldc,
                   int M, int N, int K, int relu)
{
    __shared__ float sA[BKK][BM + 4];
    __shared__ float sB[BKK][BN + 4];

    const int bm = blockIdx.y * BM;
    const int bn = blockIdx.x * BN;
    const int tx = threadIdx.x & 15;
    const int ty = threadIdx.x >> 4;

    float acc[4][4];
    #pragma unroll
    for (int i = 0; i < 4; i++)
        #pragma unroll
        for (int j = 0; j < 4; j++) acc[i][j] = 0.f;

    for (int k0 = 0; k0 < K; k0 += BKK) {
        // load A tile (BM x BKK)
        for (int i = threadIdx.x; i < BM * BKK; i += 256) {
            int r = i >> 4, c = i & 15;
            int gk = k0 + c;
            float v = 0.f;
            if (gk < K) v = A[(size_t)(bm + r) * lda + gk];
            sA[c][r] = v;
        }
        // load W tile (BN x BKK)
        for (int i = threadIdx.x; i < BN * BKK; i += 256) {
            int r = i >> 4, c = i & 15;
            int gk = k0 + c;
            int gn = bn + r;
            float v = 0.f;
            if (gk < K && gn < N) v = W[(size_t)gn * K + gk];
            sB[c][r] = v;
        }
        __syncthreads();

        #pragma unroll
        for (int kk = 0; kk < BKK; kk++) {
            float a[4], b[4];
            #pragma unroll
            for (int i = 0; i < 4; i++) a[i] = sA[kk][ty * 4 + i];
            #pragma unroll
            for (int j = 0; j < 4; j++) b[j] = sB[kk][tx * 4 + j];
            #pragma unroll
            for (int i = 0; i < 4; i++)
                #pragma unroll
                for (int j = 0; j < 4; j++) acc[i][j] = fmaf(a[i], b[j], acc[i][j]);
        }
        __syncthreads();
    }

    #pragma unroll
    for (int i = 0; i < 4; i++) {
        int m = bm + ty * 4 + i;
        #pragma unroll
        for (int j = 0; j < 4; j++) {
            int n = bn + tx * 4 + j;
            if (n < N) {
                float v = acc[i][j] + bias[n];
                if (relu) v = fmaxf(v, 0.f);
                C[(size_t)m * ldc + n] = v;
            }
        }
    }
}

// ---------------- embedding gather + mean-pool (L=4) -----------------------
// grid: (BATCH/4, N_TABLES), 256 threads: 4 samples x 64 dims
// NOTE: lS_i arrives as int32 (harness downcasts int64 inputs).
__global__ __launch_bounds__(256)
void emb_pool_kernel(const int* __restrict__ lS_i,
                     const float* __restrict__ tables,
                     float* __restrict__ feat)
{
    const int t = blockIdx.y;
    const int b = blockIdx.x * 4 + (threadIdx.x >> 6);
    const int d = threadIdx.x & 63;

    const float* tab = tables + (size_t)t * ROWS_T * EDIM;
    const int* idx = lS_i + (size_t)t * BATCH * POOL_L + (size_t)b * POOL_L;

    float acc = 0.f;
    #pragma unroll
    for (int l = 0; l < POOL_L; l++) {
        int r = idx[l];
        acc += tab[(size_t)r * EDIM + d];
    }
    feat[(size_t)b * FEAT_LD + (size_t)(t + 1) * EDIM + d] = acc * 0.25f;
}

// ---------------- interaction: lower-tri pairwise dots + concat ------------
// one block per sample, 128 threads
__global__ __launch_bounds__(128)
void interact_kernel(const float* __restrict__ feat, float* __restrict__ R)
{
    __shared__ float s[NFEAT * 65];   // padded rows to dodge bank conflicts
    const int b = blockIdx.x;
    const float* fb = feat + (size_t)b * FEAT_LD;

    for (int i = threadIdx.x; i < FEAT_LD; i += 128) {
        int f = i >> 6, d = i & 63;
        s[f * 65 + d] = fb[i];
    }
    __syncthreads();

    float* Rb = R + (size_t)b * RDIM;
    if (threadIdx.x < EDIM) Rb[threadIdx.x] = s[threadIdx.x];

    for (int p = threadIdx.x; p < NPAIRS; p += 128) {
        // invert p -> (i, j) with i>j, row-major tril order
        int i = (int)floorf((1.f + sqrtf(8.f * (float)p + 1.f)) * 0.5f);
        while (i * (i - 1) / 2 > p) i--;
        while ((i + 1) * i / 2 <= p) i++;
        int j = p - i * (i - 1) / 2;

        const float* ri = s + i * 65;
        const float* rj = s + j * 65;
        float acc = 0.f;
        #pragma unroll
        for (int k = 0; k < EDIM; k++) acc = fmaf(ri[k], rj[k], acc);
        Rb[EDIM + p] = acc;
    }
}

// ---------------- final layer: N=1 GEMV (256 -> 1) --------------------------
__global__ __launch_bounds__(256)
void final_layer(const float* __restrict__ z2, const float* __restrict__ w,
                 const float* __restrict__ bias, float* __restrict__ out)
{
    int warp = (blockIdx.x * blockDim.x + threadIdx.x) >> 5;
    int lane = threadIdx.x & 31;
    if (warp >= BATCH) return;
    const float* row = z2 + (size_t)warp * 256;
    float acc = 0.f;
    #pragma unroll
    for (int k = lane; k < 256; k += 32) acc = fmaf(row[k], w[k], acc);
    #pragma unroll
    for (int off = 16; off > 0; off >>= 1)
        acc += __shfl_down_sync(0xffffffffu, acc, off);
    if (lane == 0) out[warp] = acc + bias[0];
}

// ---------------- launcher --------------------------------------------------
extern "C" void kernel_launch(void* const* d_in, const int* in_sizes, int n_in,
                              void* d_out, int out_size)
{
    const float* dense_x = (const float*)d_in[0];
    // d_in[1] = lS_o (unused: offsets are uniform arange*L)
    const int*   lS_i    = (const int*)d_in[2];      // int64 in ref -> int32 buffer
    const float* emb     = (const float*)d_in[3];
    const float *bw0 = (const float*)d_in[4],  *bb0 = (const float*)d_in[5];
    const float *bw1 = (const float*)d_in[6],  *bb1 = (const float*)d_in[7];
    const float *bw2 = (const float*)d_in[8],  *bb2 = (const float*)d_in[9];
    const float *tw0 = (const float*)d_in[10], *tb0 = (const float*)d_in[11];
    const float *tw1 = (const float*)d_in[12], *tb1 = (const float*)d_in[13];
    const float *tw2 = (const float*)d_in[14], *tb2 = (const float*)d_in[15];
    float* out = (float*)d_out;

    float *x1, *x2, *feat, *R, *z1, *z2;
    cudaGetSymbolAddress((void**)&x1,   g_x1);
    cudaGetSymbolAddress((void**)&x2,   g_x2);
    cudaGetSymbolAddress((void**)&feat, g_feat);
    cudaGetSymbolAddress((void**)&R,    g_R);
    cudaGetSymbolAddress((void**)&z1,   g_z1);
    cudaGetSymbolAddress((void**)&z2,   g_z2);

    dim3 blk(256);

    // bottom MLP: 13 -> 512 -> 256 -> 64  (last writes into feat slot 0)
    gemm_bias_act<<<dim3(512 / BN, BATCH / BM), blk>>>(dense_x, 13, bw0, bb0, x1, 512, BATCH, 512, 13, 1);
    gemm_bias_act<<<dim3(256 / BN, BATCH / BM), blk>>>(x1, 512, bw1, bb1, x2, 256, BATCH, 256, 512, 1);
    gemm_bias_act<<<dim3(64 / BN,  BATCH / BM), blk>>>(x2, 256, bw2, bb2, feat, FEAT_LD, BATCH, 64, 256, 1);

    // embeddings (independent of bottom MLP)
    emb_pool_kernel<<<dim3(BATCH / 4, N_TABLES), blk>>>(lS_i, emb, feat);

    // interaction -> R [B, 415]
    interact_kernel<<<BATCH, 128>>>(feat, R);

    // top MLP: 415 -> 512 -> 256 -> 1
    gemm_bias_act<<<dim3(512 / BN, BATCH / BM), blk>>>(R, RDIM, tw0, tb0, z1, 512, BATCH, 512, RDIM, 1);
    gemm_bias_act<<<dim3(256 / BN, BATCH / BM), blk>>>(z1, 512, tw1, tb1, z2, 256, BATCH, 256, 512, 1);
    final_layer<<<BATCH * 32 / 256, blk>>>(z2, tw2, tb2, out);
}

// round 6
// speedup vs baseline: 1.8816x; 1.8816x over previous
#include <cuda_runtime.h>
#include <cuda_bf16.h>
#include <math.h>

#define N_TABLES 26
#define ROWS_T   100001
#define EDIM     64
#define BATCH    8192
#define POOL_L   4
#define NFEAT    (N_TABLES + 1)            // 27
#define NPAIRS   (NFEAT * (NFEAT - 1) / 2) // 351
#define RDIM     (EDIM + NPAIRS)           // 415
#define FEAT_LD  (NFEAT * EDIM)            // 1728

// ---------------- scratch (device globals; no allocation allowed) ----------
__device__ float g_x1[BATCH * 512];
__device__ float g_x2[BATCH * 256];
__device__ float g_feat[BATCH * FEAT_LD];
__device__ float g_R[BATCH * RDIM];
__device__ float g_z1[BATCH * 512];
__device__ float g_z2[BATCH * 256];

// ============================================================================
// Big SGEMM: C[M,N] = relu?(A[M,K] @ W[N,K]^T + bias)
// 128x128 tile, BK=8, 8x8 micro-tile, double-buffered smem, reg-staged prefetch
// Requires: M % 128 == 0, N % 128 == 0 (K arbitrary).
// ============================================================================
#define TM 128
#define TN 128
#define TK 8

__global__ __launch_bounds__(256, 2)
void sgemm128(const float* __restrict__ A, int lda,
              const float* __restrict__ W,           // [N,K] row-major
              const float* __restrict__ bias,
              float* __restrict__ C, int ldc,
              int K, int relu)
{
    __shared__ float sA[2][TK][TM];
    __shared__ float sB[2][TK][TN];

    const int bm  = blockIdx.y * TM;
    const int bn  = blockIdx.x * TN;
    const int tid = threadIdx.x;
    const int lr  = tid >> 1;            // 0..127: row within tile (A m-row / W n-row)
    const int lk  = (tid & 1) * 4;       // 0 or 4: k sub-offset

    const float* Arow = A + (size_t)(bm + lr) * lda;
    const float* Wrow = W + (size_t)(bn + lr) * K;

    float acc[8][8];
    #pragma unroll
    for (int i = 0; i < 8; i++)
        #pragma unroll
        for (int j = 0; j < 8; j++) acc[i][j] = 0.f;

    // prologue: tile 0
    #pragma unroll
    for (int i = 0; i < 4; i++) {
        int k = lk + i;
        sA[0][lk + i][lr] = (k < K) ? Arow[k] : 0.f;
        sB[0][lk + i][lr] = (k < K) ? Wrow[k] : 0.f;
    }
    __syncthreads();

    const int ty = tid >> 4;             // 0..15
    const int tx = tid & 15;             // 0..15
    const int nt = (K + TK - 1) / TK;
    int buf = 0;

    for (int t = 1; t <= nt; t++) {
        float ra[4], rb[4];
        if (t < nt) {
            const int k0 = t * TK;
            #pragma unroll
            for (int i = 0; i < 4; i++) {
                int k = k0 + lk + i;
                ra[i] = (k < K) ? Arow[k] : 0.f;
                rb[i] = (k < K) ? Wrow[k] : 0.f;
            }
        }

        #pragma unroll
        for (int kk = 0; kk < TK; kk++) {
            float4 a0 = *(const float4*)&sA[buf][kk][ty * 8];
            float4 a1 = *(const float4*)&sA[buf][kk][ty * 8 + 4];
            float4 b0 = *(const float4*)&sB[buf][kk][tx * 8];
            float4 b1 = *(const float4*)&sB[buf][kk][tx * 8 + 4];
            float a[8] = {a0.x, a0.y, a0.z, a0.w, a1.x, a1.y, a1.z, a1.w};
            float b[8] = {b0.x, b0.y, b0.z, b0.w, b1.x, b1.y, b1.z, b1.w};
            #pragma unroll
            for (int i = 0; i < 8; i++)
                #pragma unroll
                for (int j = 0; j < 8; j++)
                    acc[i][j] = fmaf(a[i], b[j], acc[i][j]);
        }

        if (t < nt) {
            #pragma unroll
            for (int i = 0; i < 4; i++) {
                sA[buf ^ 1][lk + i][lr] = ra[i];
                sB[buf ^ 1][lk + i][lr] = rb[i];
            }
        }
        __syncthreads();
        buf ^= 1;
    }

    // epilogue: bias + optional relu, float4 stores
    #pragma unroll
    for (int i = 0; i < 8; i++) {
        const int m = bm + ty * 8 + i;
        float* Cr = C + (size_t)m * ldc + bn + tx * 8;
        #pragma unroll
        for (int h = 0; h < 2; h++) {
            float4 v;
            float* vp = &v.x;
            #pragma unroll
            for (int j = 0; j < 4; j++) {
                float x = acc[i][h * 4 + j] + bias[bn + tx * 8 + h * 4 + j];
                if (relu) x = fmaxf(x, 0.f);
                vp[j] = x;
            }
            *(float4*)(Cr + h * 4) = v;
        }
    }
}

// ============================================================================
// Small/odd-shape SGEMM (64x64x16 tile) — used for K=13 and N=64 layers
// ============================================================================
#define BM 64
#define BN 64
#define BKK 16

__global__ __launch_bounds__(256)
void gemm_bias_act(const float* __restrict__ A, int lda,
                   const float* __restrict__ W,
                   const float* __restrict__ bias,
                   float* __restrict__ C, int ldc,
                   int M, int N, int K, int relu)
{
    __shared__ float sA[BKK][BM + 4];
    __shared__ float sB[BKK][BN + 4];

    const int bm = blockIdx.y * BM;
    const int bn = blockIdx.x * BN;
    const int tx = threadIdx.x & 15;
    const int ty = threadIdx.x >> 4;

    float acc[4][4];
    #pragma unroll
    for (int i = 0; i < 4; i++)
        #pragma unroll
        for (int j = 0; j < 4; j++) acc[i][j] = 0.f;

    for (int k0 = 0; k0 < K; k0 += BKK) {
        for (int i = threadIdx.x; i < BM * BKK; i += 256) {
            int r = i >> 4, c = i & 15;
            int gk = k0 + c;
            sA[c][r] = (gk < K) ? A[(size_t)(bm + r) * lda + gk] : 0.f;
        }
        for (int i = threadIdx.x; i < BN * BKK; i += 256) {
            int r = i >> 4, c = i & 15;
            int gk = k0 + c;
            int gn = bn + r;
            sB[c][r] = (gk < K && gn < N) ? W[(size_t)gn * K + gk] : 0.f;
        }
        __syncthreads();

        #pragma unroll
        for (int kk = 0; kk < BKK; kk++) {
            float a[4], b[4];
            #pragma unroll
            for (int i = 0; i < 4; i++) a[i] = sA[kk][ty * 4 + i];
            #pragma unroll
            for (int j = 0; j < 4; j++) b[j] = sB[kk][tx * 4 + j];
            #pragma unroll
            for (int i = 0; i < 4; i++)
                #pragma unroll
                for (int j = 0; j < 4; j++) acc[i][j] = fmaf(a[i], b[j], acc[i][j]);
        }
        __syncthreads();
    }

    #pragma unroll
    for (int i = 0; i < 4; i++) {
        int m = bm + ty * 4 + i;
        #pragma unroll
        for (int j = 0; j < 4; j++) {
            int n = bn + tx * 4 + j;
            if (n < N) {
                float v = acc[i][j] + bias[n];
                if (relu) v = fmaxf(v, 0.f);
                C[(size_t)m * ldc + n] = v;
            }
        }
    }
}

// ---------------- embedding gather + mean-pool (L=4) -----------------------
// 1 warp = 1 (table, sample): 32 threads x float2 = 64 dims, 256B/row coalesced
__global__ __launch_bounds__(256)
void emb_pool_kernel(const int* __restrict__ lS_i,
                     const float* __restrict__ tables,
                     float* __restrict__ feat)
{
    const int t    = blockIdx.y;
    const int b    = blockIdx.x * 8 + (threadIdx.x >> 5);
    const int lane = threadIdx.x & 31;

    const float* tab = tables + (size_t)t * ROWS_T * EDIM;
    const int*   idx = lS_i + (size_t)t * BATCH * POOL_L + (size_t)b * POOL_L;

    float2 acc = make_float2(0.f, 0.f);
    #pragma unroll
    for (int l = 0; l < POOL_L; l++) {
        int r = idx[l];
        float2 v = *(const float2*)(tab + (size_t)r * EDIM + lane * 2);
        acc.x += v.x; acc.y += v.y;
    }
    acc.x *= 0.25f; acc.y *= 0.25f;
    *(float2*)(feat + (size_t)b * FEAT_LD + (size_t)(t + 1) * EDIM + lane * 2) = acc;
}

// ---------------- interaction: lower-tri pairwise dots + concat ------------
__global__ __launch_bounds__(128)
void interact_kernel(const float* __restrict__ feat, float* __restrict__ R)
{
    __shared__ float s[NFEAT * 65];
    const int b = blockIdx.x;
    const float* fb = feat + (size_t)b * FEAT_LD;

    for (int i = threadIdx.x; i < FEAT_LD; i += 128) {
        int f = i >> 6, d = i & 63;
        s[f * 65 + d] = fb[i];
    }
    __syncthreads();

    float* Rb = R + (size_t)b * RDIM;
    if (threadIdx.x < EDIM) Rb[threadIdx.x] = s[threadIdx.x];

    for (int p = threadIdx.x; p < NPAIRS; p += 128) {
        int i = (int)floorf((1.f + sqrtf(8.f * (float)p + 1.f)) * 0.5f);
        while (i * (i - 1) / 2 > p) i--;
        while ((i + 1) * i / 2 <= p) i++;
        int j = p - i * (i - 1) / 2;

        const float* ri = s + i * 65;
        const float* rj = s + j * 65;
        float acc = 0.f;
        #pragma unroll
        for (int k = 0; k < EDIM; k++) acc = fmaf(ri[k], rj[k], acc);
        Rb[EDIM + p] = acc;
    }
}

// ---------------- final layer: N=1 GEMV (256 -> 1) --------------------------
__global__ __launch_bounds__(256)
void final_layer(const float* __restrict__ z2, const float* __restrict__ w,
                 const float* __restrict__ bias, float* __restrict__ out)
{
    int warp = (blockIdx.x * blockDim.x + threadIdx.x) >> 5;
    int lane = threadIdx.x & 31;
    if (warp >= BATCH) return;
    const float* row = z2 + (size_t)warp * 256;
    float acc = 0.f;
    #pragma unroll
    for (int k = lane; k < 256; k += 32) acc = fmaf(row[k], w[k], acc);
    #pragma unroll
    for (int off = 16; off > 0; off >>= 1)
        acc += __shfl_down_sync(0xffffffffu, acc, off);
    if (lane == 0) out[warp] = acc + bias[0];
}

// ---------------- launcher --------------------------------------------------
extern "C" void kernel_launch(void* const* d_in, const int* in_sizes, int n_in,
                              void* d_out, int out_size)
{
    const float* dense_x = (const float*)d_in[0];
    const int*   lS_i    = (const int*)d_in[2];
    const float* emb     = (const float*)d_in[3];
    const float *bw0 = (const float*)d_in[4],  *bb0 = (const float*)d_in[5];
    const float *bw1 = (const float*)d_in[6],  *bb1 = (const float*)d_in[7];
    const float *bw2 = (const float*)d_in[8],  *bb2 = (const float*)d_in[9];
    const float *tw0 = (const float*)d_in[10], *tb0 = (const float*)d_in[11];
    const float *tw1 = (const float*)d_in[12], *tb1 = (const float*)d_in[13];
    const float *tw2 = (const float*)d_in[14], *tb2 = (const float*)d_in[15];
    float* out = (float*)d_out;

    float *x1, *x2, *feat, *R, *z1, *z2;
    cudaGetSymbolAddress((void**)&x1,   g_x1);
    cudaGetSymbolAddress((void**)&x2,   g_x2);
    cudaGetSymbolAddress((void**)&feat, g_feat);
    cudaGetSymbolAddress((void**)&R,    g_R);
    cudaGetSymbolAddress((void**)&z1,   g_z1);
    cudaGetSymbolAddress((void**)&z2,   g_z2);

    dim3 blk(256);

    // bottom MLP
    gemm_bias_act<<<dim3(512 / BN, BATCH / BM), blk>>>(dense_x, 13, bw0, bb0, x1, 512, BATCH, 512, 13, 1);
    sgemm128<<<dim3(256 / TN, BATCH / TM), blk>>>(x1, 512, bw1, bb1, x2, 256, 512, 1);
    gemm_bias_act<<<dim3(64 / BN, BATCH / BM), blk>>>(x2, 256, bw2, bb2, feat, FEAT_LD, BATCH, 64, 256, 1);

    // embeddings
    emb_pool_kernel<<<dim3(BATCH / 8, N_TABLES), blk>>>(lS_i, emb, feat);

    // interaction -> R [B, 415]
    interact_kernel<<<BATCH, 128>>>(feat, R);

    // top MLP: 415 -> 512 -> 256 -> 1
    sgemm128<<<dim3(512 / TN, BATCH / TM), blk>>>(R, RDIM, tw0, tb0, z1, 512, RDIM, 1);
    sgemm128<<<dim3(256 / TN, BATCH / TM), blk>>>(z1, 512, tw1, tb1, z2, 256, 512, 1);
    final_layer<<<BATCH * 32 / 256, blk>>>(z2, tw2, tb2, out);
}

// round 8
// speedup vs baseline: 3.2129x; 1.7075x over previous
#include <cuda_runtime.h>
#include <cuda_bf16.h>
#include <math.h>
#include <stdint.h>

#define N_TABLES 26
#define ROWS_T   100001
#define EDIM     64
#define BATCH    8192
#define POOL_L   4
#define NFEAT    (N_TABLES + 1)            // 27
#define NPAIRS   (NFEAT * (NFEAT - 1) / 2) // 351
#define RDIM     (EDIM + NPAIRS)           // 415
#define RLD      416                       // padded row stride for R
#define FEAT_LD  (NFEAT * EDIM)            // 1728

// ---------------- scratch (device globals; no allocation allowed) ----------
__device__ float g_x1[BATCH * 512];
__device__ float g_x2[BATCH * 256];
__device__ float g_feat[BATCH * FEAT_LD];
__device__ float g_R[BATCH * RLD];
__device__ float g_z1[BATCH * 512];
__device__ float g_z2[BATCH * 256];
__device__ float g_w0p[512 * RLD];          // top_w0 padded to K=416

// ============================================================================
// TF32 tensor-core GEMM: C[M,N] = relu?(A[M,K] @ W[N,K]^T + bias)
// 128x128 tile, BK=16, 8 warps (2x4), warp tile 64x32, mma.sync m16n8k8.tf32
// Requires: M%128==0, N%128==0, K%16==0, A/W rows 16B-aligned (lda,ldw %4==0)
// ============================================================================
#define GTM 128
#define GTN 128
#define GBK 16
#define SLD 20          // smem row stride (floats); (4r+c)%32 distinct -> no conflicts

__device__ __forceinline__ uint32_t f2tf(float f) {
    uint32_t u;
    asm("cvt.rna.tf32.f32 %0, %1;" : "=r"(u) : "f"(f));
    return u;
}

__device__ __forceinline__ void mma_tf32(float* c, const uint32_t* a, const uint32_t* b) {
    asm volatile(
        "mma.sync.aligned.m16n8k8.row.col.f32.tf32.tf32.f32 "
        "{%0,%1,%2,%3}, {%4,%5,%6,%7}, {%8,%9}, {%0,%1,%2,%3};"
        : "+f"(c[0]), "+f"(c[1]), "+f"(c[2]), "+f"(c[3])
        : "r"(a[0]), "r"(a[1]), "r"(a[2]), "r"(a[3]), "r"(b[0]), "r"(b[1]));
}

__global__ __launch_bounds__(256)
void gemm_tf32(const float* __restrict__ A, int lda,
               const float* __restrict__ W, int ldw,
               const float* __restrict__ bias,
               float* __restrict__ C, int ldc,
               int K, int relu)
{
    __shared__ uint32_t sA[2][GTM * SLD];   // 20 KB x2
    __shared__ uint32_t sB[2][GTN * SLD];   // 20 KB x2  (total 40 KB)

    const int tid  = threadIdx.x;
    const int bm   = blockIdx.y * GTM;
    const int bn   = blockIdx.x * GTN;
    const int wid  = tid >> 5;
    const int lane = tid & 31;
    const int wm   = (wid >> 2) * 64;       // 0 or 64
    const int wn   = (wid & 3) * 32;        // 0,32,64,96
    const int lr   = lane >> 2;             // 0..7
    const int lc   = lane & 3;              // 0..3

    float acc[4][4][4];
    #pragma unroll
    for (int i = 0; i < 4; i++)
        #pragma unroll
        for (int j = 0; j < 4; j++)
            #pragma unroll
            for (int k = 0; k < 4; k++) acc[i][j][k] = 0.f;

    // tile loader: 128 rows x 16 k = 512 float4 per operand, 2 per thread
    auto load_tile = [&](int k0, int buf) {
        #pragma unroll
        for (int j = 0; j < 2; j++) {
            int idx = tid + 256 * j;
            int r   = idx >> 2;
            int c4  = (idx & 3) * 4;
            float4 va = *(const float4*)(A + (size_t)(bm + r) * lda + k0 + c4);
            float4 vb = *(const float4*)(W + (size_t)(bn + r) * ldw + k0 + c4);
            uint4 ua = make_uint4(f2tf(va.x), f2tf(va.y), f2tf(va.z), f2tf(va.w));
            uint4 ub = make_uint4(f2tf(vb.x), f2tf(vb.y), f2tf(vb.z), f2tf(vb.w));
            *(uint4*)&sA[buf][r * SLD + c4] = ua;
            *(uint4*)&sB[buf][r * SLD + c4] = ub;
        }
    };

    load_tile(0, 0);
    __syncthreads();

    const int nt = K / GBK;
    for (int t = 0; t < nt; t++) {
        const int buf = t & 1;
        if (t + 1 < nt) load_tile((t + 1) * GBK, buf ^ 1);

        #pragma unroll
        for (int ks = 0; ks < 2; ks++) {
            const int k8 = ks * 8;
            uint32_t afr[4][4], bfr[4][2];
            #pragma unroll
            for (int mf = 0; mf < 4; mf++) {
                int r = wm + mf * 16 + lr;
                int c = k8 + lc;
                afr[mf][0] = sA[buf][r * SLD + c];
                afr[mf][1] = sA[buf][(r + 8) * SLD + c];
                afr[mf][2] = sA[buf][r * SLD + c + 4];
                afr[mf][3] = sA[buf][(r + 8) * SLD + c + 4];
            }
            #pragma unroll
            for (int nf = 0; nf < 4; nf++) {
                int n = wn + nf * 8 + lr;
                int k = k8 + lc;
                bfr[nf][0] = sB[buf][n * SLD + k];
                bfr[nf][1] = sB[buf][n * SLD + k + 4];
            }
            #pragma unroll
            for (int mf = 0; mf < 4; mf++)
                #pragma unroll
                for (int nf = 0; nf < 4; nf++)
                    mma_tf32(acc[mf][nf], afr[mf], bfr[nf]);
        }
        __syncthreads();
    }

    // epilogue: c0,c1 -> (row, col..col+1), c2,c3 -> (row+8, ...)
    #pragma unroll
    for (int mf = 0; mf < 4; mf++) {
        const int row = bm + wm + mf * 16 + lr;
        #pragma unroll
        for (int nf = 0; nf < 4; nf++) {
            const int col = bn + wn + nf * 8 + lc * 2;
            float b0 = bias[col], b1 = bias[col + 1];
            float v0 = acc[mf][nf][0] + b0, v1 = acc[mf][nf][1] + b1;
            float v2 = acc[mf][nf][2] + b0, v3 = acc[mf][nf][3] + b1;
            if (relu) {
                v0 = fmaxf(v0, 0.f); v1 = fmaxf(v1, 0.f);
                v2 = fmaxf(v2, 0.f); v3 = fmaxf(v3, 0.f);
            }
            *(float2*)(C + (size_t)row * ldc + col)       = make_float2(v0, v1);
            *(float2*)(C + (size_t)(row + 8) * ldc + col) = make_float2(v2, v3);
        }
    }
}

// ---------------- pad top_w0 [512,415] -> [512,416] with zero col ----------
__global__ __launch_bounds__(256)
void pad_w0_kernel(const float* __restrict__ w, float* __restrict__ wp)
{
    int i = blockIdx.x * 256 + threadIdx.x;
    if (i < 512 * RLD) {
        int n = i / RLD, k = i % RLD;
        wp[i] = (k < RDIM) ? w[n * RDIM + k] : 0.f;
    }
}

// ============================================================================
// Small/odd-shape SGEMM (64x64x16 tile) — K=13 and N=64 layers
// ============================================================================
#define BM 64
#define BN 64
#define BKK 16

__global__ __launch_bounds__(256)
void gemm_bias_act(const float* __restrict__ A, int lda,
                   const float* __restrict__ W,
                   const float* __restrict__ bias,
                   float* __restrict__ C, int ldc,
                   int M, int N, int K, int relu)
{
    __shared__ float sA[BKK][BM + 4];
    __shared__ float sB[BKK][BN + 4];

    const int bm = blockIdx.y * BM;
    const int bn = blockIdx.x * BN;
    const int tx = threadIdx.x & 15;
    const int ty = threadIdx.x >> 4;

    float acc[4][4];
    #pragma unroll
    for (int i = 0; i < 4; i++)
        #pragma unroll
        for (int j = 0; j < 4; j++) acc[i][j] = 0.f;

    for (int k0 = 0; k0 < K; k0 += BKK) {
        for (int i = threadIdx.x; i < BM * BKK; i += 256) {
            int r = i >> 4, c = i & 15;
            int gk = k0 + c;
            sA[c][r] = (gk < K) ? A[(size_t)(bm + r) * lda + gk] : 0.f;
        }
        for (int i = threadIdx.x; i < BN * BKK; i += 256) {
            int r = i >> 4, c = i & 15;
            int gk = k0 + c;
            int gn = bn + r;
            sB[c][r] = (gk < K && gn < N) ? W[(size_t)gn * K + gk] : 0.f;
        }
        __syncthreads();

        #pragma unroll
        for (int kk = 0; kk < BKK; kk++) {
            float a[4], b[4];
            #pragma unroll
            for (int i = 0; i < 4; i++) a[i] = sA[kk][ty * 4 + i];
            #pragma unroll
            for (int j = 0; j < 4; j++) b[j] = sB[kk][tx * 4 + j];
            #pragma unroll
            for (int i = 0; i < 4; i++)
                #pragma unroll
                for (int j = 0; j < 4; j++) acc[i][j] = fmaf(a[i], b[j], acc[i][j]);
        }
        __syncthreads();
    }

    #pragma unroll
    for (int i = 0; i < 4; i++) {
        int m = bm + ty * 4 + i;
        #pragma unroll
        for (int j = 0; j < 4; j++) {
            int n = bn + tx * 4 + j;
            if (n < N) {
                float v = acc[i][j] + bias[n];
                if (relu) v = fmaxf(v, 0.f);
                C[(size_t)m * ldc + n] = v;
            }
        }
    }
}

// ---------------- embedding gather + mean-pool (L=4) -----------------------
__global__ __launch_bounds__(256)
void emb_pool_kernel(const int* __restrict__ lS_i,
                     const float* __restrict__ tables,
                     float* __restrict__ feat)
{
    const int t    = blockIdx.y;
    const int b    = blockIdx.x * 8 + (threadIdx.x >> 5);
    const int lane = threadIdx.x & 31;

    const float* tab = tables + (size_t)t * ROWS_T * EDIM;
    const int*   idx = lS_i + (size_t)t * BATCH * POOL_L + (size_t)b * POOL_L;

    float2 acc = make_float2(0.f, 0.f);
    #pragma unroll
    for (int l = 0; l < POOL_L; l++) {
        int r = idx[l];
        float2 v = *(const float2*)(tab + (size_t)r * EDIM + lane * 2);
        acc.x += v.x; acc.y += v.y;
    }
    acc.x *= 0.25f; acc.y *= 0.25f;
    *(float2*)(feat + (size_t)b * FEAT_LD + (size_t)(t + 1) * EDIM + lane * 2) = acc;
}

// ---------------- interaction: lower-tri pairwise dots + concat ------------
__global__ __launch_bounds__(128)
void interact_kernel(const float* __restrict__ feat, float* __restrict__ R)
{
    __shared__ float s[NFEAT * 65];
    const int b = blockIdx.x;
    const float* fb = feat + (size_t)b * FEAT_LD;

    for (int i = threadIdx.x; i < FEAT_LD; i += 128) {
        int f = i >> 6, d = i & 63;
        s[f * 65 + d] = fb[i];
    }
    __syncthreads();

    float* Rb = R + (size_t)b * RLD;
    if (threadIdx.x < EDIM) Rb[threadIdx.x] = s[threadIdx.x];
    if (threadIdx.x == 0)   Rb[RDIM] = 0.f;   // zero pad column 415

    for (int p = threadIdx.x; p < NPAIRS; p += 128) {
        int i = (int)floorf((1.f + sqrtf(8.f * (float)p + 1.f)) * 0.5f);
        while (i * (i - 1) / 2 > p) i--;
        while ((i + 1) * i / 2 <= p) i++;
        int j = p - i * (i - 1) / 2;

        const float* ri = s + i * 65;
        const float* rj = s + j * 65;
        float acc = 0.f;
        #pragma unroll
        for (int k = 0; k < EDIM; k++) acc = fmaf(ri[k], rj[k], acc);
        Rb[EDIM + p] = acc;
    }
}

// ---------------- final layer: N=1 GEMV (256 -> 1) --------------------------
__global__ __launch_bounds__(256)
void final_layer(const float* __restrict__ z2, const float* __restrict__ w,
                 const float* __restrict__ bias, float* __restrict__ out)
{
    int warp = (blockIdx.x * blockDim.x + threadIdx.x) >> 5;
    int lane = threadIdx.x & 31;
    if (warp >= BATCH) return;
    const float* row = z2 + (size_t)warp * 256;
    float acc = 0.f;
    #pragma unroll
    for (int k = lane; k < 256; k += 32) acc = fmaf(row[k], w[k], acc);
    #pragma unroll
    for (int off = 16; off > 0; off >>= 1)
        acc += __shfl_down_sync(0xffffffffu, acc, off);
    if (lane == 0) out[warp] = acc + bias[0];
}

// ---------------- launcher --------------------------------------------------
extern "C" void kernel_launch(void* const* d_in, const int* in_sizes, int n_in,
                              void* d_out, int out_size)
{
    const float* dense_x = (const float*)d_in[0];
    const int*   lS_i    = (const int*)d_in[2];
    const float* emb     = (const float*)d_in[3];
    const float *bw0 = (const float*)d_in[4],  *bb0 = (const float*)d_in[5];
    const float *bw1 = (const float*)d_in[6],  *bb1 = (const float*)d_in[7];
    const float *bw2 = (const float*)d_in[8],  *bb2 = (const float*)d_in[9];
    const float *tw0 = (const float*)d_in[10], *tb0 = (const float*)d_in[11];
    const float *tw1 = (const float*)d_in[12], *tb1 = (const float*)d_in[13];
    const float *tw2 = (const float*)d_in[14], *tb2 = (const float*)d_in[15];
    float* out = (float*)d_out;

    float *x1, *x2, *feat, *R, *z1, *z2, *w0p;
    cudaGetSymbolAddress((void**)&x1,   g_x1);
    cudaGetSymbolAddress((void**)&x2,   g_x2);
    cudaGetSymbolAddress((void**)&feat, g_feat);
    cudaGetSymbolAddress((void**)&R,    g_R);
    cudaGetSymbolAddress((void**)&z1,   g_z1);
    cudaGetSymbolAddress((void**)&z2,   g_z2);
    cudaGetSymbolAddress((void**)&w0p,  g_w0p);

    dim3 blk(256);

    // pad top_w0 (independent; overlaps other work in graph replay ordering)
    pad_w0_kernel<<<(512 * RLD + 255) / 256, blk>>>(tw0, w0p);

    // bottom MLP: 13 -> 512 -> 256 -> 64
    gemm_bias_act<<<dim3(512 / BN, BATCH / BM), blk>>>(dense_x, 13, bw0, bb0, x1, 512, BATCH, 512, 13, 1);
    gemm_tf32<<<dim3(256 / GTN, BATCH / GTM), blk>>>(x1, 512, bw1, 512, bb1, x2, 256, 512, 1);
    gemm_bias_act<<<dim3(64 / BN, BATCH / BM), blk>>>(x2, 256, bw2, bb2, feat, FEAT_LD, BATCH, 64, 256, 1);

    // embeddings
    emb_pool_kernel<<<dim3(BATCH / 8, N_TABLES), blk>>>(lS_i, emb, feat);

    // interaction -> R [B, 416(pad)]
    interact_kernel<<<BATCH, 128>>>(feat, R);

    // top MLP: 416(pad) -> 512 -> 256 -> 1
    gemm_tf32<<<dim3(512 / GTN, BATCH / GTM), blk>>>(R, RLD, w0p, RLD, tb0, z1, 512, RLD, 1);
    gemm_tf32<<<dim3(256 / GTN, BATCH / GTM), blk>>>(z1, 512, tw1, 512, tb1, z2, 256, 512, 1);
    final_layer<<<BATCH * 32 / 256, blk>>>(z2, tw2, tb2, out);
}

// round 9
// speedup vs baseline: 4.0883x; 1.2725x over previous
#include <cuda_runtime.h>
#include <cuda_bf16.h>
#include <math.h>
#include <stdint.h>

#define N_TABLES 26
#define ROWS_T   100001
#define EDIM     64
#define BATCH    8192
#define POOL_L   4
#define NFEAT    (N_TABLES + 1)            // 27
#define NPAIRS   (NFEAT * (NFEAT - 1) / 2) // 351
#define RDIM     (EDIM + NPAIRS)           // 415
#define RLD      416                       // padded row stride for R
#define FEAT_LD  (NFEAT * EDIM)            // 1728

// ---------------- scratch (device globals; no allocation allowed) ----------
__device__ float g_x1[BATCH * 512];
__device__ float g_x2[BATCH * 256];
__device__ float g_feat[BATCH * FEAT_LD];
__device__ float g_R[BATCH * RLD];
__device__ float g_z1[BATCH * 512];
__device__ float g_z2[BATCH * 256];
__device__ float g_w0p[512 * RLD];          // top_w0 padded to K=416

// ---------------- tf32 helpers ---------------------------------------------
__device__ __forceinline__ uint32_t f2tf(float f) {
    uint32_t u;
    asm("cvt.rna.tf32.f32 %0, %1;" : "=r"(u) : "f"(f));
    return u;
}

__device__ __forceinline__ void mma_tf32(float* c, const uint32_t* a, const uint32_t* b) {
    asm volatile(
        "mma.sync.aligned.m16n8k8.row.col.f32.tf32.tf32.f32 "
        "{%0,%1,%2,%3}, {%4,%5,%6,%7}, {%8,%9}, {%0,%1,%2,%3};"
        : "+f"(c[0]), "+f"(c[1]), "+f"(c[2]), "+f"(c[3])
        : "r"(a[0]), "r"(a[1]), "r"(a[2]), "r"(a[3]), "r"(b[0]), "r"(b[1]));
}

// ============================================================================
// TF32 GEMM 128x128: C[M,N] = relu?(A[M,K] @ W[N,K]^T + bias)
// BK=16, 8 warps (2x4), warp tile 64x32. M%128==0, N%128==0, K%16==0.
// ============================================================================
#define GTM 128
#define GTN 128
#define GBK 16
#define SLD 20

__global__ __launch_bounds__(256)
void gemm_tf32(const float* __restrict__ A, int lda,
               const float* __restrict__ W, int ldw,
               const float* __restrict__ bias,
               float* __restrict__ C, int ldc,
               int K, int relu)
{
    __shared__ uint32_t sA[2][GTM * SLD];
    __shared__ uint32_t sB[2][GTN * SLD];

    const int tid  = threadIdx.x;
    const int bm   = blockIdx.y * GTM;
    const int bn   = blockIdx.x * GTN;
    const int wid  = tid >> 5;
    const int lane = tid & 31;
    const int wm   = (wid >> 2) * 64;
    const int wn   = (wid & 3) * 32;
    const int lr   = lane >> 2;
    const int lc   = lane & 3;

    float acc[4][4][4];
    #pragma unroll
    for (int i = 0; i < 4; i++)
        #pragma unroll
        for (int j = 0; j < 4; j++)
            #pragma unroll
            for (int k = 0; k < 4; k++) acc[i][j][k] = 0.f;

    auto load_tile = [&](int k0, int buf) {
        #pragma unroll
        for (int j = 0; j < 2; j++) {
            int idx = tid + 256 * j;
            int r   = idx >> 2;
            int c4  = (idx & 3) * 4;
            float4 va = *(const float4*)(A + (size_t)(bm + r) * lda + k0 + c4);
            float4 vb = *(const float4*)(W + (size_t)(bn + r) * ldw + k0 + c4);
            *(uint4*)&sA[buf][r * SLD + c4] = make_uint4(f2tf(va.x), f2tf(va.y), f2tf(va.z), f2tf(va.w));
            *(uint4*)&sB[buf][r * SLD + c4] = make_uint4(f2tf(vb.x), f2tf(vb.y), f2tf(vb.z), f2tf(vb.w));
        }
    };

    load_tile(0, 0);
    __syncthreads();

    const int nt = K / GBK;
    for (int t = 0; t < nt; t++) {
        const int buf = t & 1;
        if (t + 1 < nt) load_tile((t + 1) * GBK, buf ^ 1);

        #pragma unroll
        for (int ks = 0; ks < 2; ks++) {
            const int k8 = ks * 8;
            uint32_t afr[4][4], bfr[4][2];
            #pragma unroll
            for (int mf = 0; mf < 4; mf++) {
                int r = wm + mf * 16 + lr;
                int c = k8 + lc;
                afr[mf][0] = sA[buf][r * SLD + c];
                afr[mf][1] = sA[buf][(r + 8) * SLD + c];
                afr[mf][2] = sA[buf][r * SLD + c + 4];
                afr[mf][3] = sA[buf][(r + 8) * SLD + c + 4];
            }
            #pragma unroll
            for (int nf = 0; nf < 4; nf++) {
                int n = wn + nf * 8 + lr;
                int k = k8 + lc;
                bfr[nf][0] = sB[buf][n * SLD + k];
                bfr[nf][1] = sB[buf][n * SLD + k + 4];
            }
            #pragma unroll
            for (int mf = 0; mf < 4; mf++)
                #pragma unroll
                for (int nf = 0; nf < 4; nf++)
                    mma_tf32(acc[mf][nf], afr[mf], bfr[nf]);
        }
        __syncthreads();
    }

    #pragma unroll
    for (int mf = 0; mf < 4; mf++) {
        const int row = bm + wm + mf * 16 + lr;
        #pragma unroll
        for (int nf = 0; nf < 4; nf++) {
            const int col = bn + wn + nf * 8 + lc * 2;
            float b0 = bias[col], b1 = bias[col + 1];
            float v0 = acc[mf][nf][0] + b0, v1 = acc[mf][nf][1] + b1;
            float v2 = acc[mf][nf][2] + b0, v3 = acc[mf][nf][3] + b1;
            if (relu) {
                v0 = fmaxf(v0, 0.f); v1 = fmaxf(v1, 0.f);
                v2 = fmaxf(v2, 0.f); v3 = fmaxf(v3, 0.f);
            }
            *(float2*)(C + (size_t)row * ldc + col)       = make_float2(v0, v1);
            *(float2*)(C + (size_t)(row + 8) * ldc + col) = make_float2(v2, v3);
        }
    }
}

// ============================================================================
// TF32 GEMM 128x64 (for N=64): 8 warps (4x2), warp tile 32x32
// ============================================================================
__global__ __launch_bounds__(256)
void gemm_tf32_n64(const float* __restrict__ A, int lda,
                   const float* __restrict__ W, int ldw,
                   const float* __restrict__ bias,
                   float* __restrict__ C, int ldc,
                   int K, int relu)
{
    __shared__ uint32_t sA[2][128 * SLD];
    __shared__ uint32_t sB[2][64 * SLD];

    const int tid  = threadIdx.x;
    const int bm   = blockIdx.y * 128;
    const int wid  = tid >> 5;
    const int lane = tid & 31;
    const int wm   = (wid >> 1) * 32;    // 0,32,64,96
    const int wn   = (wid & 1) * 32;     // 0,32
    const int lr   = lane >> 2;
    const int lc   = lane & 3;

    float acc[2][4][4];
    #pragma unroll
    for (int i = 0; i < 2; i++)
        #pragma unroll
        for (int j = 0; j < 4; j++)
            #pragma unroll
            for (int k = 0; k < 4; k++) acc[i][j][k] = 0.f;

    auto load_tile = [&](int k0, int buf) {
        #pragma unroll
        for (int j = 0; j < 2; j++) {       // A: 512 float4
            int idx = tid + 256 * j;
            int r   = idx >> 2;
            int c4  = (idx & 3) * 4;
            float4 va = *(const float4*)(A + (size_t)(bm + r) * lda + k0 + c4);
            *(uint4*)&sA[buf][r * SLD + c4] = make_uint4(f2tf(va.x), f2tf(va.y), f2tf(va.z), f2tf(va.w));
        }
        {                                    // B: 256 float4
            int r  = tid >> 2;
            int c4 = (tid & 3) * 4;
            float4 vb = *(const float4*)(W + (size_t)r * ldw + k0 + c4);
            *(uint4*)&sB[buf][r * SLD + c4] = make_uint4(f2tf(vb.x), f2tf(vb.y), f2tf(vb.z), f2tf(vb.w));
        }
    };

    load_tile(0, 0);
    __syncthreads();

    const int nt = K / GBK;
    for (int t = 0; t < nt; t++) {
        const int buf = t & 1;
        if (t + 1 < nt) load_tile((t + 1) * GBK, buf ^ 1);

        #pragma unroll
        for (int ks = 0; ks < 2; ks++) {
            const int k8 = ks * 8;
            uint32_t afr[2][4], bfr[4][2];
            #pragma unroll
            for (int mf = 0; mf < 2; mf++) {
                int r = wm + mf * 16 + lr;
                int c = k8 + lc;
                afr[mf][0] = sA[buf][r * SLD + c];
                afr[mf][1] = sA[buf][(r + 8) * SLD + c];
                afr[mf][2] = sA[buf][r * SLD + c + 4];
                afr[mf][3] = sA[buf][(r + 8) * SLD + c + 4];
            }
            #pragma unroll
            for (int nf = 0; nf < 4; nf++) {
                int n = wn + nf * 8 + lr;
                int k = k8 + lc;
                bfr[nf][0] = sB[buf][n * SLD + k];
                bfr[nf][1] = sB[buf][n * SLD + k + 4];
            }
            #pragma unroll
            for (int mf = 0; mf < 2; mf++)
                #pragma unroll
                for (int nf = 0; nf < 4; nf++)
                    mma_tf32(acc[mf][nf], afr[mf], bfr[nf]);
        }
        __syncthreads();
    }

    #pragma unroll
    for (int mf = 0; mf < 2; mf++) {
        const int row = bm + wm + mf * 16 + lr;
        #pragma unroll
        for (int nf = 0; nf < 4; nf++) {
            const int col = wn + nf * 8 + lc * 2;
            float b0 = bias[col], b1 = bias[col + 1];
            float v0 = acc[mf][nf][0] + b0, v1 = acc[mf][nf][1] + b1;
            float v2 = acc[mf][nf][2] + b0, v3 = acc[mf][nf][3] + b1;
            if (relu) {
                v0 = fmaxf(v0, 0.f); v1 = fmaxf(v1, 0.f);
                v2 = fmaxf(v2, 0.f); v3 = fmaxf(v3, 0.f);
            }
            *(float2*)(C + (size_t)row * ldc + col)       = make_float2(v0, v1);
            *(float2*)(C + (size_t)(row + 8) * ldc + col) = make_float2(v2, v3);
        }
    }
}

// ---------------- bot0: x1 = relu(dense_x @ bw0^T + b0), K=13 --------------
// weights resident in smem; 32 batch rows per block, 2 cols per thread
__global__ __launch_bounds__(256)
void bot0_kernel(const float* __restrict__ x, const float* __restrict__ w,
                 const float* __restrict__ bias, float* __restrict__ out)
{
    __shared__ float sw[13][512];
    __shared__ float sb[512];
    __shared__ float sx[32][13];

    const int tid = threadIdx.x;
    for (int i = tid; i < 512 * 13; i += 256) {
        int c = i % 512, k = i / 512;
        sw[k][c] = w[c * 13 + k];
    }
    for (int i = tid; i < 512; i += 256) sb[i] = bias[i];
    for (int i = tid; i < 32 * 13; i += 256) {
        int r = i / 13, k = i % 13;
        sx[r][k] = x[(size_t)(blockIdx.x * 32 + r) * 13 + k];
    }
    __syncthreads();

    const int c0 = tid * 2;
    #pragma unroll 4
    for (int r = 0; r < 32; r++) {
        float a0 = sb[c0], a1 = sb[c0 + 1];
        #pragma unroll
        for (int k = 0; k < 13; k++) {
            float xv = sx[r][k];
            a0 = fmaf(xv, sw[k][c0],     a0);
            a1 = fmaf(xv, sw[k][c0 + 1], a1);
        }
        a0 = fmaxf(a0, 0.f); a1 = fmaxf(a1, 0.f);
        *(float2*)(out + (size_t)(blockIdx.x * 32 + r) * 512 + c0) = make_float2(a0, a1);
    }
}

// ---------------- pad top_w0 [512,415] -> [512,416] with zero col ----------
__global__ __launch_bounds__(256)
void pad_w0_kernel(const float* __restrict__ w, float* __restrict__ wp)
{
    int i = blockIdx.x * 256 + threadIdx.x;
    if (i < 512 * RLD) {
        int n = i / RLD, k = i % RLD;
        wp[i] = (k < RDIM) ? w[n * RDIM + k] : 0.f;
    }
}

// ---------------- embedding gather + mean-pool (L=4) -----------------------
__global__ __launch_bounds__(256)
void emb_pool_kernel(const int* __restrict__ lS_i,
                     const float* __restrict__ tables,
                     float* __restrict__ feat)
{
    const int t    = blockIdx.y;
    const int b    = blockIdx.x * 8 + (threadIdx.x >> 5);
    const int lane = threadIdx.x & 31;

    const float* tab = tables + (size_t)t * ROWS_T * EDIM;
    const int*   idx = lS_i + (size_t)t * BATCH * POOL_L + (size_t)b * POOL_L;

    float2 acc = make_float2(0.f, 0.f);
    #pragma unroll
    for (int l = 0; l < POOL_L; l++) {
        int r = idx[l];
        float2 v = *(const float2*)(tab + (size_t)r * EDIM + lane * 2);
        acc.x += v.x; acc.y += v.y;
    }
    acc.x *= 0.25f; acc.y *= 0.25f;
    *(float2*)(feat + (size_t)b * FEAT_LD + (size_t)(t + 1) * EDIM + lane * 2) = acc;
}

// ============================================================================
// Interaction via tensor cores: per sample Z = F F^T (32x32x64 tf32 MMA),
// extract strict lower triangle. 4 samples/block, 1 warp/sample.
// ============================================================================
#define ISLD 68

__global__ __launch_bounds__(128)
void interact_mma(const float* __restrict__ feat, float* __restrict__ R)
{
    __shared__ uint32_t s[4][32 * ISLD];   // ~34.8 KB

    const int wid  = threadIdx.x >> 5;
    const int lane = threadIdx.x & 31;
    const int b    = blockIdx.x * 4 + wid;
    const int lr   = lane >> 2;
    const int lc   = lane & 3;

    const float* fb = feat + (size_t)b * FEAT_LD;
    uint32_t* ss = s[wid];

    // load 27x64 as tf32 (float4 granularity: 27*16 = 432 quads)
    for (int i = lane; i < NFEAT * 16; i += 32) {
        int r  = i >> 4;
        int c4 = (i & 15) * 4;
        float4 v = *(const float4*)(fb + r * EDIM + c4);
        *(uint4*)&ss[r * ISLD + c4] = make_uint4(f2tf(v.x), f2tf(v.y), f2tf(v.z), f2tf(v.w));
    }
    // zero pad rows 27..31 (5*16 = 80 quads)
    for (int i = lane; i < 5 * 16; i += 32) {
        int r  = NFEAT + (i >> 4);
        int c4 = (i & 15) * 4;
        *(uint4*)&ss[r * ISLD + c4] = make_uint4(0, 0, 0, 0);
    }
    __syncwarp();

    float acc[2][4][4];
    #pragma unroll
    for (int i = 0; i < 2; i++)
        #pragma unroll
        for (int j = 0; j < 4; j++)
            #pragma unroll
            for (int k = 0; k < 4; k++) acc[i][j][k] = 0.f;

    #pragma unroll
    for (int k8 = 0; k8 < EDIM; k8 += 8) {
        uint32_t afr[2][4], bfr[4][2];
        #pragma unroll
        for (int mf = 0; mf < 2; mf++) {
            int r = mf * 16 + lr;
            int c = k8 + lc;
            afr[mf][0] = ss[r * ISLD + c];
            afr[mf][1] = ss[(r + 8) * ISLD + c];
            afr[mf][2] = ss[r * ISLD + c + 4];
            afr[mf][3] = ss[(r + 8) * ISLD + c + 4];
        }
        #pragma unroll
        for (int nf = 0; nf < 4; nf++) {
            int n = nf * 8 + lr;
            int k = k8 + lc;
            bfr[nf][0] = ss[n * ISLD + k];
            bfr[nf][1] = ss[n * ISLD + k + 4];
        }
        #pragma unroll
        for (int mf = 0; mf < 2; mf++)
            #pragma unroll
            for (int nf = 0; nf < 4; nf++)
                mma_tf32(acc[mf][nf], afr[mf], bfr[nf]);
    }

    float* Rb = R + (size_t)b * RLD;
    Rb[lane]      = fb[lane];          // copy x (feat row 0)
    Rb[lane + 32] = fb[lane + 32];
    if (lane == 0) Rb[RDIM] = 0.f;     // pad col 415

    #pragma unroll
    for (int mf = 0; mf < 2; mf++) {
        #pragma unroll
        for (int nf = 0; nf < 4; nf++) {
            int r0 = mf * 16 + lr, r1 = r0 + 8;
            int c0 = nf * 8 + lc * 2, c1 = c0 + 1;
            if (r0 < NFEAT && c0 < r0) Rb[EDIM + r0 * (r0 - 1) / 2 + c0] = acc[mf][nf][0];
            if (r0 < NFEAT && c1 < r0) Rb[EDIM + r0 * (r0 - 1) / 2 + c1] = acc[mf][nf][1];
            if (r1 < NFEAT && c0 < r1) Rb[EDIM + r1 * (r1 - 1) / 2 + c0] = acc[mf][nf][2];
            if (r1 < NFEAT && c1 < r1) Rb[EDIM + r1 * (r1 - 1) / 2 + c1] = acc[mf][nf][3];
        }
    }
}

// ---------------- final layer: N=1 GEMV (256 -> 1) --------------------------
__global__ __launch_bounds__(256)
void final_layer(const float* __restrict__ z2, const float* __restrict__ w,
                 const float* __restrict__ bias, float* __restrict__ out)
{
    int warp = (blockIdx.x * blockDim.x + threadIdx.x) >> 5;
    int lane = threadIdx.x & 31;
    if (warp >= BATCH) return;
    const float* row = z2 + (size_t)warp * 256;
    float acc = 0.f;
    #pragma unroll
    for (int k = lane; k < 256; k += 32) acc = fmaf(row[k], w[k], acc);
    #pragma unroll
    for (int off = 16; off > 0; off >>= 1)
        acc += __shfl_down_sync(0xffffffffu, acc, off);
    if (lane == 0) out[warp] = acc + bias[0];
}

// ---------------- launcher --------------------------------------------------
extern "C" void kernel_launch(void* const* d_in, const int* in_sizes, int n_in,
                              void* d_out, int out_size)
{
    const float* dense_x = (const float*)d_in[0];
    const int*   lS_i    = (const int*)d_in[2];
    const float* emb     = (const float*)d_in[3];
    const float *bw0 = (const float*)d_in[4],  *bb0 = (const float*)d_in[5];
    const float *bw1 = (const float*)d_in[6],  *bb1 = (const float*)d_in[7];
    const float *bw2 = (const float*)d_in[8],  *bb2 = (const float*)d_in[9];
    const float *tw0 = (const float*)d_in[10], *tb0 = (const float*)d_in[11];
    const float *tw1 = (const float*)d_in[12], *tb1 = (const float*)d_in[13];
    const float *tw2 = (const float*)d_in[14], *tb2 = (const float*)d_in[15];
    float* out = (float*)d_out;

    float *x1, *x2, *feat, *R, *z1, *z2, *w0p;
    cudaGetSymbolAddress((void**)&x1,   g_x1);
    cudaGetSymbolAddress((void**)&x2,   g_x2);
    cudaGetSymbolAddress((void**)&feat, g_feat);
    cudaGetSymbolAddress((void**)&R,    g_R);
    cudaGetSymbolAddress((void**)&z1,   g_z1);
    cudaGetSymbolAddress((void**)&z2,   g_z2);
    cudaGetSymbolAddress((void**)&w0p,  g_w0p);

    dim3 blk(256);

    pad_w0_kernel<<<(512 * RLD + 255) / 256, blk>>>(tw0, w0p);

    // bottom MLP: 13 -> 512 -> 256 -> 64
    bot0_kernel<<<BATCH / 32, blk>>>(dense_x, bw0, bb0, x1);
    gemm_tf32<<<dim3(256 / GTN, BATCH / GTM), blk>>>(x1, 512, bw1, 512, bb1, x2, 256, 512, 1);
    gemm_tf32_n64<<<dim3(1, BATCH / 128), blk>>>(x2, 256, bw2, 256, bb2, feat, FEAT_LD, 256, 1);

    // embeddings
    emb_pool_kernel<<<dim3(BATCH / 8, N_TABLES), blk>>>(lS_i, emb, feat);

    // interaction -> R [B, 416(pad)]
    interact_mma<<<BATCH / 4, 128>>>(feat, R);

    // top MLP: 416(pad) -> 512 -> 256 -> 1
    gemm_tf32<<<dim3(512 / GTN, BATCH / GTM), blk>>>(R, RLD, w0p, RLD, tb0, z1, 512, RLD, 1);
    gemm_tf32<<<dim3(256 / GTN, BATCH / GTM), blk>>>(z1, 512, tw1, 512, tb1, z2, 256, 512, 1);
    final_layer<<<BATCH * 32 / 256, blk>>>(z2, tw2, tb2, out);
}

// round 10
// speedup vs baseline: 4.2233x; 1.0330x over previous
#include <cuda_runtime.h>
#include <cuda_bf16.h>
#include <math.h>
#include <stdint.h>

#define N_TABLES 26
#define ROWS_T   100001
#define EDIM     64
#define BATCH    8192
#define POOL_L   4
#define NFEAT    (N_TABLES + 1)            // 27
#define NPAIRS   (NFEAT * (NFEAT - 1) / 2) // 351
#define RDIM     (EDIM + NPAIRS)           // 415
#define RLD      416                       // padded row stride for R
#define FEAT_LD  (NFEAT * EDIM)            // 1728

// ---------------- scratch (device globals; no allocation allowed) ----------
__device__ float g_x1[BATCH * 512];
__device__ float g_x2[BATCH * 256];
__device__ float g_feat[BATCH * FEAT_LD];
__device__ float g_R[BATCH * RLD];
__device__ float g_z1[BATCH * 512];
__device__ float g_w0p[512 * RLD];          // top_w0 padded to K=416

// ---------------- tf32 helpers ---------------------------------------------
__device__ __forceinline__ uint32_t f2tf(float f) {
    uint32_t u;
    asm("cvt.rna.tf32.f32 %0, %1;" : "=r"(u) : "f"(f));
    return u;
}

__device__ __forceinline__ void mma_tf32(float* c, const uint32_t* a, const uint32_t* b) {
    asm volatile(
        "mma.sync.aligned.m16n8k8.row.col.f32.tf32.tf32.f32 "
        "{%0,%1,%2,%3}, {%4,%5,%6,%7}, {%8,%9}, {%0,%1,%2,%3};"
        : "+f"(c[0]), "+f"(c[1]), "+f"(c[2]), "+f"(c[3])
        : "r"(a[0]), "r"(a[1]), "r"(a[2]), "r"(a[3]), "r"(b[0]), "r"(b[1]));
}

// ============================================================================
// TF32 GEMM 128x128: C[M,N] = relu?(A[M,K] @ W[N,K]^T + bias)
// BK=16, 8 warps (2x4), warp tile 64x32. M%128==0, N%128==0, K%16==0.
// ============================================================================
#define GTM 128
#define GTN 128
#define GBK 16
#define SLD 20

__global__ __launch_bounds__(256)
void gemm_tf32(const float* __restrict__ A, int lda,
               const float* __restrict__ W, int ldw,
               const float* __restrict__ bias,
               float* __restrict__ C, int ldc,
               int K, int relu)
{
    __shared__ uint32_t sA[2][GTM * SLD];
    __shared__ uint32_t sB[2][GTN * SLD];

    const int tid  = threadIdx.x;
    const int bm   = blockIdx.y * GTM;
    const int bn   = blockIdx.x * GTN;
    const int wid  = tid >> 5;
    const int lane = tid & 31;
    const int wm   = (wid >> 2) * 64;
    const int wn   = (wid & 3) * 32;
    const int lr   = lane >> 2;
    const int lc   = lane & 3;

    float acc[4][4][4];
    #pragma unroll
    for (int i = 0; i < 4; i++)
        #pragma unroll
        for (int j = 0; j < 4; j++)
            #pragma unroll
            for (int k = 0; k < 4; k++) acc[i][j][k] = 0.f;

    auto load_tile = [&](int k0, int buf) {
        #pragma unroll
        for (int j = 0; j < 2; j++) {
            int idx = tid + 256 * j;
            int r   = idx >> 2;
            int c4  = (idx & 3) * 4;
            float4 va = *(const float4*)(A + (size_t)(bm + r) * lda + k0 + c4);
            float4 vb = *(const float4*)(W + (size_t)(bn + r) * ldw + k0 + c4);
            *(uint4*)&sA[buf][r * SLD + c4] = make_uint4(f2tf(va.x), f2tf(va.y), f2tf(va.z), f2tf(va.w));
            *(uint4*)&sB[buf][r * SLD + c4] = make_uint4(f2tf(vb.x), f2tf(vb.y), f2tf(vb.z), f2tf(vb.w));
        }
    };

    load_tile(0, 0);
    __syncthreads();

    const int nt = K / GBK;
    for (int t = 0; t < nt; t++) {
        const int buf = t & 1;
        if (t + 1 < nt) load_tile((t + 1) * GBK, buf ^ 1);

        #pragma unroll
        for (int ks = 0; ks < 2; ks++) {
            const int k8 = ks * 8;
            uint32_t afr[4][4], bfr[4][2];
            #pragma unroll
            for (int mf = 0; mf < 4; mf++) {
                int r = wm + mf * 16 + lr;
                int c = k8 + lc;
                afr[mf][0] = sA[buf][r * SLD + c];
                afr[mf][1] = sA[buf][(r + 8) * SLD + c];
                afr[mf][2] = sA[buf][r * SLD + c + 4];
                afr[mf][3] = sA[buf][(r + 8) * SLD + c + 4];
            }
            #pragma unroll
            for (int nf = 0; nf < 4; nf++) {
                int n = wn + nf * 8 + lr;
                int k = k8 + lc;
                bfr[nf][0] = sB[buf][n * SLD + k];
                bfr[nf][1] = sB[buf][n * SLD + k + 4];
            }
            #pragma unroll
            for (int mf = 0; mf < 4; mf++)
                #pragma unroll
                for (int nf = 0; nf < 4; nf++)
                    mma_tf32(acc[mf][nf], afr[mf], bfr[nf]);
        }
        __syncthreads();
    }

    #pragma unroll
    for (int mf = 0; mf < 4; mf++) {
        const int row = bm + wm + mf * 16 + lr;
        #pragma unroll
        for (int nf = 0; nf < 4; nf++) {
            const int col = bn + wn + nf * 8 + lc * 2;
            float b0 = bias[col], b1 = bias[col + 1];
            float v0 = acc[mf][nf][0] + b0, v1 = acc[mf][nf][1] + b1;
            float v2 = acc[mf][nf][2] + b0, v3 = acc[mf][nf][3] + b1;
            if (relu) {
                v0 = fmaxf(v0, 0.f); v1 = fmaxf(v1, 0.f);
                v2 = fmaxf(v2, 0.f); v3 = fmaxf(v3, 0.f);
            }
            *(float2*)(C + (size_t)row * ldc + col)       = make_float2(v0, v1);
            *(float2*)(C + (size_t)(row + 8) * ldc + col) = make_float2(v2, v3);
        }
    }
}

// ============================================================================
// TF32 GEMM 128x128 + fused final GEMV: out[row] += sum_col relu(..)*w2[col]
// (atomicAdd row partials; out pre-initialized to final bias)
// ============================================================================
__global__ __launch_bounds__(256)
void gemm_tf32_final(const float* __restrict__ A, int lda,
                     const float* __restrict__ W, int ldw,
                     const float* __restrict__ bias,
                     const float* __restrict__ w2,
                     float* __restrict__ out,
                     int K)
{
    __shared__ uint32_t sA[2][GTM * SLD];
    __shared__ uint32_t sB[2][GTN * SLD];

    const int tid  = threadIdx.x;
    const int bm   = blockIdx.y * GTM;
    const int bn   = blockIdx.x * GTN;
    const int wid  = tid >> 5;
    const int lane = tid & 31;
    const int wm   = (wid >> 2) * 64;
    const int wn   = (wid & 3) * 32;
    const int lr   = lane >> 2;
    const int lc   = lane & 3;

    float acc[4][4][4];
    #pragma unroll
    for (int i = 0; i < 4; i++)
        #pragma unroll
        for (int j = 0; j < 4; j++)
            #pragma unroll
            for (int k = 0; k < 4; k++) acc[i][j][k] = 0.f;

    auto load_tile = [&](int k0, int buf) {
        #pragma unroll
        for (int j = 0; j < 2; j++) {
            int idx = tid + 256 * j;
            int r   = idx >> 2;
            int c4  = (idx & 3) * 4;
            float4 va = *(const float4*)(A + (size_t)(bm + r) * lda + k0 + c4);
            float4 vb = *(const float4*)(W + (size_t)(bn + r) * ldw + k0 + c4);
            *(uint4*)&sA[buf][r * SLD + c4] = make_uint4(f2tf(va.x), f2tf(va.y), f2tf(va.z), f2tf(va.w));
            *(uint4*)&sB[buf][r * SLD + c4] = make_uint4(f2tf(vb.x), f2tf(vb.y), f2tf(vb.z), f2tf(vb.w));
        }
    };

    load_tile(0, 0);
    __syncthreads();

    const int nt = K / GBK;
    for (int t = 0; t < nt; t++) {
        const int buf = t & 1;
        if (t + 1 < nt) load_tile((t + 1) * GBK, buf ^ 1);

        #pragma unroll
        for (int ks = 0; ks < 2; ks++) {
            const int k8 = ks * 8;
            uint32_t afr[4][4], bfr[4][2];
            #pragma unroll
            for (int mf = 0; mf < 4; mf++) {
                int r = wm + mf * 16 + lr;
                int c = k8 + lc;
                afr[mf][0] = sA[buf][r * SLD + c];
                afr[mf][1] = sA[buf][(r + 8) * SLD + c];
                afr[mf][2] = sA[buf][r * SLD + c + 4];
                afr[mf][3] = sA[buf][(r + 8) * SLD + c + 4];
            }
            #pragma unroll
            for (int nf = 0; nf < 4; nf++) {
                int n = wn + nf * 8 + lr;
                int k = k8 + lc;
                bfr[nf][0] = sB[buf][n * SLD + k];
                bfr[nf][1] = sB[buf][n * SLD + k + 4];
            }
            #pragma unroll
            for (int mf = 0; mf < 4; mf++)
                #pragma unroll
                for (int nf = 0; nf < 4; nf++)
                    mma_tf32(acc[mf][nf], afr[mf], bfr[nf]);
        }
        __syncthreads();
    }

    #pragma unroll
    for (int mf = 0; mf < 4; mf++) {
        const int row = bm + wm + mf * 16 + lr;
        float p0 = 0.f, p1 = 0.f;
        #pragma unroll
        for (int nf = 0; nf < 4; nf++) {
            const int col = bn + wn + nf * 8 + lc * 2;
            float b0 = bias[col], b1 = bias[col + 1];
            float w0 = w2[col],   w1 = w2[col + 1];
            float v0 = fmaxf(acc[mf][nf][0] + b0, 0.f);
            float v1 = fmaxf(acc[mf][nf][1] + b1, 0.f);
            float v2 = fmaxf(acc[mf][nf][2] + b0, 0.f);
            float v3 = fmaxf(acc[mf][nf][3] + b1, 0.f);
            p0 = fmaf(v0, w0, fmaf(v1, w1, p0));
            p1 = fmaf(v2, w0, fmaf(v3, w1, p1));
        }
        atomicAdd(&out[row], p0);
        atomicAdd(&out[row + 8], p1);
    }
}

// ============================================================================
// TF32 GEMM 64x64 (bot2, N=64): 8 warps (2x4), warp tile 32x16, grid (1,128)
// ============================================================================
__global__ __launch_bounds__(256)
void gemm_tf32_64(const float* __restrict__ A, int lda,
                  const float* __restrict__ W, int ldw,
                  const float* __restrict__ bias,
                  float* __restrict__ C, int ldc,
                  int K)
{
    __shared__ uint32_t sA[2][64 * SLD];
    __shared__ uint32_t sB[2][64 * SLD];

    const int tid  = threadIdx.x;
    const int bm   = blockIdx.y * 64;
    const int wid  = tid >> 5;
    const int lane = tid & 31;
    const int wm   = (wid >> 2) * 32;    // 0,32
    const int wn   = (wid & 3) * 16;     // 0,16,32,48
    const int lr   = lane >> 2;
    const int lc   = lane & 3;

    float acc[2][2][4];
    #pragma unroll
    for (int i = 0; i < 2; i++)
        #pragma unroll
        for (int j = 0; j < 2; j++)
            #pragma unroll
            for (int k = 0; k < 4; k++) acc[i][j][k] = 0.f;

    auto load_tile = [&](int k0, int buf) {
        int r  = tid >> 2;
        int c4 = (tid & 3) * 4;
        float4 va = *(const float4*)(A + (size_t)(bm + r) * lda + k0 + c4);
        float4 vb = *(const float4*)(W + (size_t)r * ldw + k0 + c4);
        *(uint4*)&sA[buf][r * SLD + c4] = make_uint4(f2tf(va.x), f2tf(va.y), f2tf(va.z), f2tf(va.w));
        *(uint4*)&sB[buf][r * SLD + c4] = make_uint4(f2tf(vb.x), f2tf(vb.y), f2tf(vb.z), f2tf(vb.w));
    };

    load_tile(0, 0);
    __syncthreads();

    const int nt = K / GBK;
    for (int t = 0; t < nt; t++) {
        const int buf = t & 1;
        if (t + 1 < nt) load_tile((t + 1) * GBK, buf ^ 1);

        #pragma unroll
        for (int ks = 0; ks < 2; ks++) {
            const int k8 = ks * 8;
            uint32_t afr[2][4], bfr[2][2];
            #pragma unroll
            for (int mf = 0; mf < 2; mf++) {
                int r = wm + mf * 16 + lr;
                int c = k8 + lc;
                afr[mf][0] = sA[buf][r * SLD + c];
                afr[mf][1] = sA[buf][(r + 8) * SLD + c];
                afr[mf][2] = sA[buf][r * SLD + c + 4];
                afr[mf][3] = sA[buf][(r + 8) * SLD + c + 4];
            }
            #pragma unroll
            for (int nf = 0; nf < 2; nf++) {
                int n = wn + nf * 8 + lr;
                int k = k8 + lc;
                bfr[nf][0] = sB[buf][n * SLD + k];
                bfr[nf][1] = sB[buf][n * SLD + k + 4];
            }
            #pragma unroll
            for (int mf = 0; mf < 2; mf++)
                #pragma unroll
                for (int nf = 0; nf < 2; nf++)
                    mma_tf32(acc[mf][nf], afr[mf], bfr[nf]);
        }
        __syncthreads();
    }

    #pragma unroll
    for (int mf = 0; mf < 2; mf++) {
        const int row = bm + wm + mf * 16 + lr;
        #pragma unroll
        for (int nf = 0; nf < 2; nf++) {
            const int col = wn + nf * 8 + lc * 2;
            float b0 = bias[col], b1 = bias[col + 1];
            float v0 = fmaxf(acc[mf][nf][0] + b0, 0.f);
            float v1 = fmaxf(acc[mf][nf][1] + b1, 0.f);
            float v2 = fmaxf(acc[mf][nf][2] + b0, 0.f);
            float v3 = fmaxf(acc[mf][nf][3] + b1, 0.f);
            *(float2*)(C + (size_t)row * ldc + col)       = make_float2(v0, v1);
            *(float2*)(C + (size_t)(row + 8) * ldc + col) = make_float2(v2, v3);
        }
    }
}

// ---------------- bot0: x1 = relu(dense_x @ bw0^T + b0), K=13 --------------
__global__ __launch_bounds__(256)
void bot0_kernel(const float* __restrict__ x, const float* __restrict__ w,
                 const float* __restrict__ bias, float* __restrict__ out)
{
    __shared__ float sw[13][512];
    __shared__ float sb[512];
    __shared__ float sx[32][13];

    const int tid = threadIdx.x;
    for (int i = tid; i < 512 * 13; i += 256) {
        int c = i % 512, k = i / 512;
        sw[k][c] = w[c * 13 + k];
    }
    for (int i = tid; i < 512; i += 256) sb[i] = bias[i];
    for (int i = tid; i < 32 * 13; i += 256) {
        int r = i / 13, k = i % 13;
        sx[r][k] = x[(size_t)(blockIdx.x * 32 + r) * 13 + k];
    }
    __syncthreads();

    const int c0 = tid * 2;
    #pragma unroll 4
    for (int r = 0; r < 32; r++) {
        float a0 = sb[c0], a1 = sb[c0 + 1];
        #pragma unroll
        for (int k = 0; k < 13; k++) {
            float xv = sx[r][k];
            a0 = fmaf(xv, sw[k][c0],     a0);
            a1 = fmaf(xv, sw[k][c0 + 1], a1);
        }
        a0 = fmaxf(a0, 0.f); a1 = fmaxf(a1, 0.f);
        *(float2*)(out + (size_t)(blockIdx.x * 32 + r) * 512 + c0) = make_float2(a0, a1);
    }
}

// ---------------- pad top_w0 [512,415] -> [512,416] with zero col ----------
__global__ __launch_bounds__(256)
void pad_w0_kernel(const float* __restrict__ w, float* __restrict__ wp)
{
    int i = blockIdx.x * 256 + threadIdx.x;
    if (i < 512 * RLD) {
        int n = i / RLD, k = i % RLD;
        wp[i] = (k < RDIM) ? w[n * RDIM + k] : 0.f;
    }
}

// ---------------- out init: out[i] = final bias ----------------------------
__global__ __launch_bounds__(256)
void out_init_kernel(float* __restrict__ out, const float* __restrict__ b)
{
    int i = blockIdx.x * 256 + threadIdx.x;
    if (i < BATCH) out[i] = b[0];
}

// ---------------- embedding gather + mean-pool (L=4) -----------------------
__global__ __launch_bounds__(256)
void emb_pool_kernel(const int* __restrict__ lS_i,
                     const float* __restrict__ tables,
                     float* __restrict__ feat)
{
    const int t    = blockIdx.y;
    const int b    = blockIdx.x * 8 + (threadIdx.x >> 5);
    const int lane = threadIdx.x & 31;

    const float* tab = tables + (size_t)t * ROWS_T * EDIM;
    const int*   idx = lS_i + (size_t)t * BATCH * POOL_L + (size_t)b * POOL_L;

    float2 acc = make_float2(0.f, 0.f);
    #pragma unroll
    for (int l = 0; l < POOL_L; l++) {
        int r = idx[l];
        float2 v = *(const float2*)(tab + (size_t)r * EDIM + lane * 2);
        acc.x += v.x; acc.y += v.y;
    }
    acc.x *= 0.25f; acc.y *= 0.25f;
    *(float2*)(feat + (size_t)b * FEAT_LD + (size_t)(t + 1) * EDIM + lane * 2) = acc;
}

// ============================================================================
// Interaction: per sample Z = F F^T (32x32x64 tf32 MMA), strict lower tri.
// 4 samples/block, 1 warp/sample.
// ============================================================================
#define ISLD 68

__global__ __launch_bounds__(128)
void interact_mma(const float* __restrict__ feat, float* __restrict__ R)
{
    __shared__ uint32_t s[4][32 * ISLD];

    const int wid  = threadIdx.x >> 5;
    const int lane = threadIdx.x & 31;
    const int b    = blockIdx.x * 4 + wid;
    const int lr   = lane >> 2;
    const int lc   = lane & 3;

    const float* fb = feat + (size_t)b * FEAT_LD;
    uint32_t* ss = s[wid];

    for (int i = lane; i < NFEAT * 16; i += 32) {
        int r  = i >> 4;
        int c4 = (i & 15) * 4;
        float4 v = *(const float4*)(fb + r * EDIM + c4);
        *(uint4*)&ss[r * ISLD + c4] = make_uint4(f2tf(v.x), f2tf(v.y), f2tf(v.z), f2tf(v.w));
    }
    for (int i = lane; i < 5 * 16; i += 32) {
        int r  = NFEAT + (i >> 4);
        int c4 = (i & 15) * 4;
        *(uint4*)&ss[r * ISLD + c4] = make_uint4(0, 0, 0, 0);
    }
    __syncwarp();

    float acc[2][4][4];
    #pragma unroll
    for (int i = 0; i < 2; i++)
        #pragma unroll
        for (int j = 0; j < 4; j++)
            #pragma unroll
            for (int k = 0; k < 4; k++) acc[i][j][k] = 0.f;

    #pragma unroll
    for (int k8 = 0; k8 < EDIM; k8 += 8) {
        uint32_t afr[2][4], bfr[4][2];
        #pragma unroll
        for (int mf = 0; mf < 2; mf++) {
            int r = mf * 16 + lr;
            int c = k8 + lc;
            afr[mf][0] = ss[r * ISLD + c];
            afr[mf][1] = ss[(r + 8) * ISLD + c];
            afr[mf][2] = ss[r * ISLD + c + 4];
            afr[mf][3] = ss[(r + 8) * ISLD + c + 4];
        }
        #pragma unroll
        for (int nf = 0; nf < 4; nf++) {
            int n = nf * 8 + lr;
            int k = k8 + lc;
            bfr[nf][0] = ss[n * ISLD + k];
            bfr[nf][1] = ss[n * ISLD + k + 4];
        }
        #pragma unroll
        for (int mf = 0; mf < 2; mf++)
            #pragma unroll
            for (int nf = 0; nf < 4; nf++)
                mma_tf32(acc[mf][nf], afr[mf], bfr[nf]);
    }

    float* Rb = R + (size_t)b * RLD;
    Rb[lane]      = fb[lane];
    Rb[lane + 32] = fb[lane + 32];
    if (lane == 0) Rb[RDIM] = 0.f;

    #pragma unroll
    for (int mf = 0; mf < 2; mf++) {
        #pragma unroll
        for (int nf = 0; nf < 4; nf++) {
            int r0 = mf * 16 + lr, r1 = r0 + 8;
            int c0 = nf * 8 + lc * 2, c1 = c0 + 1;
            if (r0 < NFEAT && c0 < r0) Rb[EDIM + r0 * (r0 - 1) / 2 + c0] = acc[mf][nf][0];
            if (r0 < NFEAT && c1 < r0) Rb[EDIM + r0 * (r0 - 1) / 2 + c1] = acc[mf][nf][1];
            if (r1 < NFEAT && c0 < r1) Rb[EDIM + r1 * (r1 - 1) / 2 + c0] = acc[mf][nf][2];
            if (r1 < NFEAT && c1 < r1) Rb[EDIM + r1 * (r1 - 1) / 2 + c1] = acc[mf][nf][3];
        }
    }
}

// ---------------- launcher --------------------------------------------------
extern "C" void kernel_launch(void* const* d_in, const int* in_sizes, int n_in,
                              void* d_out, int out_size)
{
    const float* dense_x = (const float*)d_in[0];
    const int*   lS_i    = (const int*)d_in[2];
    const float* emb     = (const float*)d_in[3];
    const float *bw0 = (const float*)d_in[4],  *bb0 = (const float*)d_in[5];
    const float *bw1 = (const float*)d_in[6],  *bb1 = (const float*)d_in[7];
    const float *bw2 = (const float*)d_in[8],  *bb2 = (const float*)d_in[9];
    const float *tw0 = (const float*)d_in[10], *tb0 = (const float*)d_in[11];
    const float *tw1 = (const float*)d_in[12], *tb1 = (const float*)d_in[13];
    const float *tw2 = (const float*)d_in[14], *tb2 = (const float*)d_in[15];
    float* out = (float*)d_out;

    float *x1, *x2, *feat, *R, *z1, *w0p;
    cudaGetSymbolAddress((void**)&x1,   g_x1);
    cudaGetSymbolAddress((void**)&x2,   g_x2);
    cudaGetSymbolAddress((void**)&feat, g_feat);
    cudaGetSymbolAddress((void**)&R,    g_R);
    cudaGetSymbolAddress((void**)&z1,   g_z1);
    cudaGetSymbolAddress((void**)&w0p,  g_w0p);

    // one-time side-stream + events (host objects; created on first call,
    // before the harness's capture call)
    static cudaStream_t s1 = nullptr;
    static cudaEvent_t evFork = nullptr, evJoin = nullptr;
    if (!s1) {
        cudaStreamCreateWithFlags(&s1, cudaStreamNonBlocking);
        cudaEventCreateWithFlags(&evFork, cudaEventDisableTiming);
        cudaEventCreateWithFlags(&evJoin, cudaEventDisableTiming);
    }

    dim3 blk(256);

    // fork: embedding gather + weight pad on side stream (independent of bot MLP)
    cudaEventRecord(evFork, 0);
    cudaStreamWaitEvent(s1, evFork, 0);
    emb_pool_kernel<<<dim3(BATCH / 8, N_TABLES), blk, 0, s1>>>(lS_i, emb, feat);
    pad_w0_kernel<<<(512 * RLD + 255) / 256, blk, 0, s1>>>(tw0, w0p);
    cudaEventRecord(evJoin, s1);

    // main stream: bottom MLP chain + out init
    out_init_kernel<<<(BATCH + 255) / 256, blk>>>(out, tb2);
    bot0_kernel<<<BATCH / 32, blk>>>(dense_x, bw0, bb0, x1);
    gemm_tf32<<<dim3(256 / GTN, BATCH / GTM), blk>>>(x1, 512, bw1, 512, bb1, x2, 256, 512, 1);
    gemm_tf32_64<<<dim3(1, BATCH / 64), blk>>>(x2, 256, bw2, 256, bb2, feat, FEAT_LD, 256);

    // join: interact needs feat rows 0..26; top0 needs w0p
    cudaStreamWaitEvent(0, evJoin, 0);

    interact_mma<<<BATCH / 4, 128>>>(feat, R);

    // top MLP: 416(pad) -> 512 -> 256 -> 1 (final GEMV fused into top1)
    gemm_tf32<<<dim3(512 / GTN, BATCH / GTM), blk>>>(R, RLD, w0p, RLD, tb0, z1, 512, RLD, 1);
    gemm_tf32_final<<<dim3(256 / GTN, BATCH / GTM), blk>>>(z1, 512, tw1, 512, tb1, tw2, out, 512);
}

// round 11
// speedup vs baseline: 4.9488x; 1.1718x over previous
#include <cuda_runtime.h>
#include <cuda_bf16.h>
#include <math.h>
#include <stdint.h>

#define N_TABLES 26
#define ROWS_T   100001
#define EDIM     64
#define BATCH    8192
#define POOL_L   4
#define NFEAT    (N_TABLES + 1)            // 27
#define NPAIRS   (NFEAT * (NFEAT - 1) / 2) // 351
#define RDIM     (EDIM + NPAIRS)           // 415
#define RLD      416                       // padded row stride for R
#define FEAT_LD  (NFEAT * EDIM)            // 1728

// ---------------- scratch (device globals; no allocation allowed) ----------
__device__ float g_x1[BATCH * 512];
__device__ float g_x2[BATCH * 256];
__device__ float g_feat[BATCH * FEAT_LD];
__device__ float g_R[BATCH * RLD];
__device__ float g_z1[BATCH * 512];
__device__ float g_w0p[512 * RLD];          // top_w0 padded + tf32-rounded
__device__ float g_w1c[256 * 512];          // bot_w1 tf32-rounded
__device__ float g_w2c[64 * 256];           // bot_w2 tf32-rounded
__device__ float g_wt1c[256 * 512];         // top_w1 tf32-rounded

// ---------------- tf32 helpers ---------------------------------------------
__device__ __forceinline__ uint32_t f2tf(float f) {
    uint32_t u;
    asm("cvt.rna.tf32.f32 %0, %1;" : "=r"(u) : "f"(f));
    return u;
}
__device__ __forceinline__ float f2tff(float f) { return __uint_as_float(f2tf(f)); }

__device__ __forceinline__ void mma_tf32(float* c, const uint32_t* a, const uint32_t* b) {
    asm volatile(
        "mma.sync.aligned.m16n8k8.row.col.f32.tf32.tf32.f32 "
        "{%0,%1,%2,%3}, {%4,%5,%6,%7}, {%8,%9}, {%0,%1,%2,%3};"
        : "+f"(c[0]), "+f"(c[1]), "+f"(c[2]), "+f"(c[3])
        : "r"(a[0]), "r"(a[1]), "r"(a[2]), "r"(a[3]), "r"(b[0]), "r"(b[1]));
}

__device__ __forceinline__ void cp16(void* smem_dst, const void* gsrc) {
    uint32_t s = (uint32_t)__cvta_generic_to_shared(smem_dst);
    asm volatile("cp.async.cg.shared.global [%0], [%1], 16;" :: "r"(s), "l"(gsrc));
}
#define CP_COMMIT()  asm volatile("cp.async.commit_group;")
#define CP_WAIT(n)   asm volatile("cp.async.wait_group %0;" :: "n"(n))

// ============================================================================
// TF32 GEMM 128x128, cp.async double-buffered. Inputs MUST be tf32-rounded.
// C = relu(A[M,K] @ W[N,K]^T + bias), output tf32-rounded (feeds next GEMM).
// ============================================================================
#define GTM 128
#define GTN 128
#define GBK 16
#define SLD 20

__global__ __launch_bounds__(256)
void gemm_tf32(const float* __restrict__ A, int lda,
               const float* __restrict__ W, int ldw,
               const float* __restrict__ bias,
               float* __restrict__ C, int ldc,
               int K, int round_out)
{
    __shared__ uint32_t sA[2][GTM * SLD];
    __shared__ uint32_t sB[2][GTN * SLD];

    const int tid  = threadIdx.x;
    const int bm   = blockIdx.y * GTM;
    const int bn   = blockIdx.x * GTN;
    const int wid  = tid >> 5;
    const int lane = tid & 31;
    const int wm   = (wid >> 2) * 64;
    const int wn   = (wid & 3) * 32;
    const int lr   = lane >> 2;
    const int lc   = lane & 3;

    float acc[4][4][4];
    #pragma unroll
    for (int i = 0; i < 4; i++)
        #pragma unroll
        for (int j = 0; j < 4; j++)
            #pragma unroll
            for (int k = 0; k < 4; k++) acc[i][j][k] = 0.f;

    auto issue_tile = [&](int k0, int buf) {
        #pragma unroll
        for (int j = 0; j < 2; j++) {
            int idx = tid + 256 * j;
            int r   = idx >> 2;
            int c4  = (idx & 3) * 4;
            cp16(&sA[buf][r * SLD + c4], A + (size_t)(bm + r) * lda + k0 + c4);
            cp16(&sB[buf][r * SLD + c4], W + (size_t)(bn + r) * ldw + k0 + c4);
        }
        CP_COMMIT();
    };

    issue_tile(0, 0);

    const int nt = K / GBK;
    for (int t = 0; t < nt; t++) {
        const int buf = t & 1;
        if (t + 1 < nt) { issue_tile((t + 1) * GBK, buf ^ 1); CP_WAIT(1); }
        else            { CP_WAIT(0); }
        __syncthreads();

        #pragma unroll
        for (int ks = 0; ks < 2; ks++) {
            const int k8 = ks * 8;
            uint32_t afr[4][4], bfr[4][2];
            #pragma unroll
            for (int mf = 0; mf < 4; mf++) {
                int r = wm + mf * 16 + lr;
                int c = k8 + lc;
                afr[mf][0] = sA[buf][r * SLD + c];
                afr[mf][1] = sA[buf][(r + 8) * SLD + c];
                afr[mf][2] = sA[buf][r * SLD + c + 4];
                afr[mf][3] = sA[buf][(r + 8) * SLD + c + 4];
            }
            #pragma unroll
            for (int nf = 0; nf < 4; nf++) {
                int n = wn + nf * 8 + lr;
                int k = k8 + lc;
                bfr[nf][0] = sB[buf][n * SLD + k];
                bfr[nf][1] = sB[buf][n * SLD + k + 4];
            }
            #pragma unroll
            for (int mf = 0; mf < 4; mf++)
                #pragma unroll
                for (int nf = 0; nf < 4; nf++)
                    mma_tf32(acc[mf][nf], afr[mf], bfr[nf]);
        }
        __syncthreads();
    }

    #pragma unroll
    for (int mf = 0; mf < 4; mf++) {
        const int row = bm + wm + mf * 16 + lr;
        #pragma unroll
        for (int nf = 0; nf < 4; nf++) {
            const int col = bn + wn + nf * 8 + lc * 2;
            float b0 = bias[col], b1 = bias[col + 1];
            float v0 = fmaxf(acc[mf][nf][0] + b0, 0.f);
            float v1 = fmaxf(acc[mf][nf][1] + b1, 0.f);
            float v2 = fmaxf(acc[mf][nf][2] + b0, 0.f);
            float v3 = fmaxf(acc[mf][nf][3] + b1, 0.f);
            if (round_out) { v0 = f2tff(v0); v1 = f2tff(v1); v2 = f2tff(v2); v3 = f2tff(v3); }
            *(float2*)(C + (size_t)row * ldc + col)       = make_float2(v0, v1);
            *(float2*)(C + (size_t)(row + 8) * ldc + col) = make_float2(v2, v3);
        }
    }
}

// ============================================================================
// Same pipeline + fused final GEMV epilogue: out[row] += relu(..) . w2
// ============================================================================
__global__ __launch_bounds__(256)
void gemm_tf32_final(const float* __restrict__ A, int lda,
                     const float* __restrict__ W, int ldw,
                     const float* __restrict__ bias,
                     const float* __restrict__ w2,
                     float* __restrict__ out,
                     int K)
{
    __shared__ uint32_t sA[2][GTM * SLD];
    __shared__ uint32_t sB[2][GTN * SLD];

    const int tid  = threadIdx.x;
    const int bm   = blockIdx.y * GTM;
    const int bn   = blockIdx.x * GTN;
    const int wid  = tid >> 5;
    const int lane = tid & 31;
    const int wm   = (wid >> 2) * 64;
    const int wn   = (wid & 3) * 32;
    const int lr   = lane >> 2;
    const int lc   = lane & 3;

    float acc[4][4][4];
    #pragma unroll
    for (int i = 0; i < 4; i++)
        #pragma unroll
        for (int j = 0; j < 4; j++)
            #pragma unroll
            for (int k = 0; k < 4; k++) acc[i][j][k] = 0.f;

    auto issue_tile = [&](int k0, int buf) {
        #pragma unroll
        for (int j = 0; j < 2; j++) {
            int idx = tid + 256 * j;
            int r   = idx >> 2;
            int c4  = (idx & 3) * 4;
            cp16(&sA[buf][r * SLD + c4], A + (size_t)(bm + r) * lda + k0 + c4);
            cp16(&sB[buf][r * SLD + c4], W + (size_t)(bn + r) * ldw + k0 + c4);
        }
        CP_COMMIT();
    };

    issue_tile(0, 0);

    const int nt = K / GBK;
    for (int t = 0; t < nt; t++) {
        const int buf = t & 1;
        if (t + 1 < nt) { issue_tile((t + 1) * GBK, buf ^ 1); CP_WAIT(1); }
        else            { CP_WAIT(0); }
        __syncthreads();

        #pragma unroll
        for (int ks = 0; ks < 2; ks++) {
            const int k8 = ks * 8;
            uint32_t afr[4][4], bfr[4][2];
            #pragma unroll
            for (int mf = 0; mf < 4; mf++) {
                int r = wm + mf * 16 + lr;
                int c = k8 + lc;
                afr[mf][0] = sA[buf][r * SLD + c];
                afr[mf][1] = sA[buf][(r + 8) * SLD + c];
                afr[mf][2] = sA[buf][r * SLD + c + 4];
                afr[mf][3] = sA[buf][(r + 8) * SLD + c + 4];
            }
            #pragma unroll
            for (int nf = 0; nf < 4; nf++) {
                int n = wn + nf * 8 + lr;
                int k = k8 + lc;
                bfr[nf][0] = sB[buf][n * SLD + k];
                bfr[nf][1] = sB[buf][n * SLD + k + 4];
            }
            #pragma unroll
            for (int mf = 0; mf < 4; mf++)
                #pragma unroll
                for (int nf = 0; nf < 4; nf++)
                    mma_tf32(acc[mf][nf], afr[mf], bfr[nf]);
        }
        __syncthreads();
    }

    #pragma unroll
    for (int mf = 0; mf < 4; mf++) {
        const int row = bm + wm + mf * 16 + lr;
        float p0 = 0.f, p1 = 0.f;
        #pragma unroll
        for (int nf = 0; nf < 4; nf++) {
            const int col = bn + wn + nf * 8 + lc * 2;
            float b0 = bias[col], b1 = bias[col + 1];
            float w0 = w2[col],   w1 = w2[col + 1];
            float v0 = fmaxf(acc[mf][nf][0] + b0, 0.f);
            float v1 = fmaxf(acc[mf][nf][1] + b1, 0.f);
            float v2 = fmaxf(acc[mf][nf][2] + b0, 0.f);
            float v3 = fmaxf(acc[mf][nf][3] + b1, 0.f);
            p0 = fmaf(v0, w0, fmaf(v1, w1, p0));
            p1 = fmaf(v2, w0, fmaf(v3, w1, p1));
        }
        atomicAdd(&out[row], p0);
        atomicAdd(&out[row + 8], p1);
    }
}

// ============================================================================
// TF32 GEMM 64x64 (bot2): cp.async, 8 warps (2x4), warp tile 32x16
// ============================================================================
__global__ __launch_bounds__(256)
void gemm_tf32_64(const float* __restrict__ A, int lda,
                  const float* __restrict__ W, int ldw,
                  const float* __restrict__ bias,
                  float* __restrict__ C, int ldc,
                  int K)
{
    __shared__ uint32_t sA[2][64 * SLD];
    __shared__ uint32_t sB[2][64 * SLD];

    const int tid  = threadIdx.x;
    const int bm   = blockIdx.y * 64;
    const int wid  = tid >> 5;
    const int lane = tid & 31;
    const int wm   = (wid >> 2) * 32;
    const int wn   = (wid & 3) * 16;
    const int lr   = lane >> 2;
    const int lc   = lane & 3;

    float acc[2][2][4];
    #pragma unroll
    for (int i = 0; i < 2; i++)
        #pragma unroll
        for (int j = 0; j < 2; j++)
            #pragma unroll
            for (int k = 0; k < 4; k++) acc[i][j][k] = 0.f;

    auto issue_tile = [&](int k0, int buf) {
        int r  = tid >> 2;
        int c4 = (tid & 3) * 4;
        cp16(&sA[buf][r * SLD + c4], A + (size_t)(bm + r) * lda + k0 + c4);
        cp16(&sB[buf][r * SLD + c4], W + (size_t)r * ldw + k0 + c4);
        CP_COMMIT();
    };

    issue_tile(0, 0);

    const int nt = K / GBK;
    for (int t = 0; t < nt; t++) {
        const int buf = t & 1;
        if (t + 1 < nt) { issue_tile((t + 1) * GBK, buf ^ 1); CP_WAIT(1); }
        else            { CP_WAIT(0); }
        __syncthreads();

        #pragma unroll
        for (int ks = 0; ks < 2; ks++) {
            const int k8 = ks * 8;
            uint32_t afr[2][4], bfr[2][2];
            #pragma unroll
            for (int mf = 0; mf < 2; mf++) {
                int r = wm + mf * 16 + lr;
                int c = k8 + lc;
                afr[mf][0] = sA[buf][r * SLD + c];
                afr[mf][1] = sA[buf][(r + 8) * SLD + c];
                afr[mf][2] = sA[buf][r * SLD + c + 4];
                afr[mf][3] = sA[buf][(r + 8) * SLD + c + 4];
            }
            #pragma unroll
            for (int nf = 0; nf < 2; nf++) {
                int n = wn + nf * 8 + lr;
                int k = k8 + lc;
                bfr[nf][0] = sB[buf][n * SLD + k];
                bfr[nf][1] = sB[buf][n * SLD + k + 4];
            }
            #pragma unroll
            for (int mf = 0; mf < 2; mf++)
                #pragma unroll
                for (int nf = 0; nf < 2; nf++)
                    mma_tf32(acc[mf][nf], afr[mf], bfr[nf]);
        }
        __syncthreads();
    }

    #pragma unroll
    for (int mf = 0; mf < 2; mf++) {
        const int row = bm + wm + mf * 16 + lr;
        #pragma unroll
        for (int nf = 0; nf < 2; nf++) {
            const int col = wn + nf * 8 + lc * 2;
            float b0 = bias[col], b1 = bias[col + 1];
            float v0 = f2tff(fmaxf(acc[mf][nf][0] + b0, 0.f));
            float v1 = f2tff(fmaxf(acc[mf][nf][1] + b1, 0.f));
            float v2 = f2tff(fmaxf(acc[mf][nf][2] + b0, 0.f));
            float v3 = f2tff(fmaxf(acc[mf][nf][3] + b1, 0.f));
            *(float2*)(C + (size_t)row * ldc + col)       = make_float2(v0, v1);
            *(float2*)(C + (size_t)(row + 8) * ldc + col) = make_float2(v2, v3);
        }
    }
}

// ---------------- bot0: x1 = tf32(relu(dense_x @ bw0^T + b0)), K=13 --------
__global__ __launch_bounds__(256)
void bot0_kernel(const float* __restrict__ x, const float* __restrict__ w,
                 const float* __restrict__ bias, float* __restrict__ out)
{
    __shared__ float sw[13][512];
    __shared__ float sb[512];
    __shared__ float sx[32][13];

    const int tid = threadIdx.x;
    for (int i = tid; i < 512 * 13; i += 256) {
        int c = i % 512, k = i / 512;
        sw[k][c] = w[c * 13 + k];
    }
    for (int i = tid; i < 512; i += 256) sb[i] = bias[i];
    for (int i = tid; i < 32 * 13; i += 256) {
        int r = i / 13, k = i % 13;
        sx[r][k] = x[(size_t)(blockIdx.x * 32 + r) * 13 + k];
    }
    __syncthreads();

    const int c0 = tid * 2;
    #pragma unroll 4
    for (int r = 0; r < 32; r++) {
        float a0 = sb[c0], a1 = sb[c0 + 1];
        #pragma unroll
        for (int k = 0; k < 13; k++) {
            float xv = sx[r][k];
            a0 = fmaf(xv, sw[k][c0],     a0);
            a1 = fmaf(xv, sw[k][c0 + 1], a1);
        }
        a0 = f2tff(fmaxf(a0, 0.f)); a1 = f2tff(fmaxf(a1, 0.f));
        *(float2*)(out + (size_t)(blockIdx.x * 32 + r) * 512 + c0) = make_float2(a0, a1);
    }
}

// ---------------- weight prep: tf32-rounded copies --------------------------
__global__ __launch_bounds__(256)
void cvt_copy_kernel(const float* __restrict__ src, float* __restrict__ dst, int n)
{
    int i = blockIdx.x * 256 + threadIdx.x;
    if (i < n) dst[i] = f2tff(src[i]);
}

__global__ __launch_bounds__(256)
void pad_w0_kernel(const float* __restrict__ w, float* __restrict__ wp)
{
    int i = blockIdx.x * 256 + threadIdx.x;
    if (i < 512 * RLD) {
        int n = i / RLD, k = i % RLD;
        wp[i] = (k < RDIM) ? f2tff(w[n * RDIM + k]) : 0.f;
    }
}

__global__ __launch_bounds__(256)
void out_init_kernel(float* __restrict__ out, const float* __restrict__ b)
{
    int i = blockIdx.x * 256 + threadIdx.x;
    if (i < BATCH) out[i] = b[0];
}

// ---------------- embedding gather + mean-pool, tf32-rounded output --------
__global__ __launch_bounds__(256)
void emb_pool_kernel(const int* __restrict__ lS_i,
                     const float* __restrict__ tables,
                     float* __restrict__ feat)
{
    const int t    = blockIdx.y;
    const int b    = blockIdx.x * 8 + (threadIdx.x >> 5);
    const int lane = threadIdx.x & 31;

    const float* tab = tables + (size_t)t * ROWS_T * EDIM;
    const int*   idx = lS_i + (size_t)t * BATCH * POOL_L + (size_t)b * POOL_L;

    float2 acc = make_float2(0.f, 0.f);
    #pragma unroll
    for (int l = 0; l < POOL_L; l++) {
        int r = idx[l];
        float2 v = *(const float2*)(tab + (size_t)r * EDIM + lane * 2);
        acc.x += v.x; acc.y += v.y;
    }
    acc.x = f2tff(acc.x * 0.25f); acc.y = f2tff(acc.y * 0.25f);
    *(float2*)(feat + (size_t)b * FEAT_LD + (size_t)(t + 1) * EDIM + lane * 2) = acc;
}

// ============================================================================
// Interaction: Z = F F^T per sample (feat already tf32-rounded -> raw copy)
// ============================================================================
#define ISLD 68

__global__ __launch_bounds__(128)
void interact_mma(const float* __restrict__ feat, float* __restrict__ R)
{
    __shared__ uint32_t s[4][32 * ISLD];

    const int wid  = threadIdx.x >> 5;
    const int lane = threadIdx.x & 31;
    const int b    = blockIdx.x * 4 + wid;
    const int lr   = lane >> 2;
    const int lc   = lane & 3;

    const float* fb = feat + (size_t)b * FEAT_LD;
    uint32_t* ss = s[wid];

    for (int i = lane; i < NFEAT * 16; i += 32) {
        int r  = i >> 4;
        int c4 = (i & 15) * 4;
        *(uint4*)&ss[r * ISLD + c4] = *(const uint4*)(fb + r * EDIM + c4);
    }
    for (int i = lane; i < 5 * 16; i += 32) {
        int r  = NFEAT + (i >> 4);
        int c4 = (i & 15) * 4;
        *(uint4*)&ss[r * ISLD + c4] = make_uint4(0, 0, 0, 0);
    }
    __syncwarp();

    float acc[2][4][4];
    #pragma unroll
    for (int i = 0; i < 2; i++)
        #pragma unroll
        for (int j = 0; j < 4; j++)
            #pragma unroll
            for (int k = 0; k < 4; k++) acc[i][j][k] = 0.f;

    #pragma unroll
    for (int k8 = 0; k8 < EDIM; k8 += 8) {
        uint32_t afr[2][4], bfr[4][2];
        #pragma unroll
        for (int mf = 0; mf < 2; mf++) {
            int r = mf * 16 + lr;
            int c = k8 + lc;
            afr[mf][0] = ss[r * ISLD + c];
            afr[mf][1] = ss[(r + 8) * ISLD + c];
            afr[mf][2] = ss[r * ISLD + c + 4];
            afr[mf][3] = ss[(r + 8) * ISLD + c + 4];
        }
        #pragma unroll
        for (int nf = 0; nf < 4; nf++) {
            int n = nf * 8 + lr;
            int k = k8 + lc;
            bfr[nf][0] = ss[n * ISLD + k];
            bfr[nf][1] = ss[n * ISLD + k + 4];
        }
        #pragma unroll
        for (int mf = 0; mf < 2; mf++)
            #pragma unroll
            for (int nf = 0; nf < 4; nf++)
                mma_tf32(acc[mf][nf], afr[mf], bfr[nf]);
    }

    float* Rb = R + (size_t)b * RLD;
    Rb[lane]      = fb[lane];          // feat row 0 already tf32-rounded
    Rb[lane + 32] = fb[lane + 32];
    if (lane == 0) Rb[RDIM] = 0.f;

    #pragma unroll
    for (int mf = 0; mf < 2; mf++) {
        #pragma unroll
        for (int nf = 0; nf < 4; nf++) {
            int r0 = mf * 16 + lr, r1 = r0 + 8;
            int c0 = nf * 8 + lc * 2, c1 = c0 + 1;
            if (r0 < NFEAT && c0 < r0) Rb[EDIM + r0 * (r0 - 1) / 2 + c0] = f2tff(acc[mf][nf][0]);
            if (r0 < NFEAT && c1 < r0) Rb[EDIM + r0 * (r0 - 1) / 2 + c1] = f2tff(acc[mf][nf][1]);
            if (r1 < NFEAT && c0 < r1) Rb[EDIM + r1 * (r1 - 1) / 2 + c0] = f2tff(acc[mf][nf][2]);
            if (r1 < NFEAT && c1 < r1) Rb[EDIM + r1 * (r1 - 1) / 2 + c1] = f2tff(acc[mf][nf][3]);
        }
    }
}

// ---------------- launcher --------------------------------------------------
extern "C" void kernel_launch(void* const* d_in, const int* in_sizes, int n_in,
                              void* d_out, int out_size)
{
    const float* dense_x = (const float*)d_in[0];
    const int*   lS_i    = (const int*)d_in[2];
    const float* emb     = (const float*)d_in[3];
    const float *bw0 = (const float*)d_in[4],  *bb0 = (const float*)d_in[5];
    const float *bw1 = (const float*)d_in[6],  *bb1 = (const float*)d_in[7];
    const float *bw2 = (const float*)d_in[8],  *bb2 = (const float*)d_in[9];
    const float *tw0 = (const float*)d_in[10], *tb0 = (const float*)d_in[11];
    const float *tw1 = (const float*)d_in[12], *tb1 = (const float*)d_in[13];
    const float *tw2 = (const float*)d_in[14], *tb2 = (const float*)d_in[15];
    float* out = (float*)d_out;

    float *x1, *x2, *feat, *R, *z1, *w0p, *w1c, *w2c, *wt1c;
    cudaGetSymbolAddress((void**)&x1,   g_x1);
    cudaGetSymbolAddress((void**)&x2,   g_x2);
    cudaGetSymbolAddress((void**)&feat, g_feat);
    cudaGetSymbolAddress((void**)&R,    g_R);
    cudaGetSymbolAddress((void**)&z1,   g_z1);
    cudaGetSymbolAddress((void**)&w0p,  g_w0p);
    cudaGetSymbolAddress((void**)&w1c,  g_w1c);
    cudaGetSymbolAddress((void**)&w2c,  g_w2c);
    cudaGetSymbolAddress((void**)&wt1c, g_wt1c);

    static cudaStream_t s1 = nullptr;
    static cudaEvent_t evFork = nullptr, evJoin = nullptr;
    if (!s1) {
        cudaStreamCreateWithFlags(&s1, cudaStreamNonBlocking);
        cudaEventCreateWithFlags(&evFork, cudaEventDisableTiming);
        cudaEventCreateWithFlags(&evJoin, cudaEventDisableTiming);
    }

    dim3 blk(256);

    // fork: embedding gather + top-weight prep + out init on side stream
    cudaEventRecord(evFork, 0);
    cudaStreamWaitEvent(s1, evFork, 0);
    emb_pool_kernel<<<dim3(BATCH / 8, N_TABLES), blk, 0, s1>>>(lS_i, emb, feat);
    pad_w0_kernel<<<(512 * RLD + 255) / 256, blk, 0, s1>>>(tw0, w0p);
    cvt_copy_kernel<<<(256 * 512 + 255) / 256, blk, 0, s1>>>(tw1, wt1c, 256 * 512);
    out_init_kernel<<<(BATCH + 255) / 256, blk, 0, s1>>>(out, tb2);
    cudaEventRecord(evJoin, s1);

    // main stream: bottom-weight prep + bottom MLP chain
    cvt_copy_kernel<<<(256 * 512 + 255) / 256, blk>>>(bw1, w1c, 256 * 512);
    cvt_copy_kernel<<<(64 * 256 + 255) / 256, blk>>>(bw2, w2c, 64 * 256);
    bot0_kernel<<<BATCH / 32, blk>>>(dense_x, bw0, bb0, x1);
    gemm_tf32<<<dim3(256 / GTN, BATCH / GTM), blk>>>(x1, 512, w1c, 512, bb1, x2, 256, 512, 1);
    gemm_tf32_64<<<dim3(1, BATCH / 64), blk>>>(x2, 256, w2c, 256, bb2, feat, FEAT_LD, 256);

    // join
    cudaStreamWaitEvent(0, evJoin, 0);

    interact_mma<<<BATCH / 4, 128>>>(feat, R);

    // top MLP: 416(pad) -> 512 -> 256 -> 1 (final GEMV fused)
    gemm_tf32<<<dim3(512 / GTN, BATCH / GTM), blk>>>(R, RLD, w0p, RLD, tb0, z1, 512, RLD, 1);
    gemm_tf32_final<<<dim3(256 / GTN, BATCH / GTM), blk>>>(z1, 512, wt1c, 512, tb1, tw2, out, 512);
}